// round 1
// baseline (speedup 1.0000x reference)
#include <cuda_runtime.h>
#include <math.h>

#define NLAYERS 4
#define DM      64
#define DS      128
#define DCONV   4
#define DI      128
#define NH      2
#define HD      64
#define CONVD   384
#define DPROJ   514
#define BSZ     8
#define SEQ     4096
#define BL      (BSZ*SEQ)     /* 32768 */
#define QC      64            /* chunk length */
#define NC      (SEQ/QC)      /* 64 chunks per sequence */
#define EPSV    1e-5f

/* ---------------- scratch (allocation-free: __device__ globals) ------------ */
__device__ float g_zxb [BL*(long)DPROJ];      /* in_proj output            */
__device__ float g_xbc [BL*(long)CONVD];      /* post-conv xBC (x,B,C)     */
__device__ float g_dt  [BSZ*NH*SEQ];          /* softplus dt               */
__device__ float g_lacc[BSZ*NH*SEQ];          /* local (per-chunk) cumsum  */
__device__ float g_atot[BSZ*NH*NC];           /* per-chunk total decay     */
__device__ float g_S   [(long)BSZ*NH*NC*HD*DS]; /* chunk state contribution */
__device__ float g_hst [(long)BSZ*NH*NC*HD*DS]; /* state at chunk start     */
__device__ float g_y   [BL*(long)DI];         /* SSM output                */

__device__ __forceinline__ float siluf(float v){ return v / (1.f + __expf(-v)); }

/* ---------------- init: copy x into residual stream (d_out) --------------- */
__global__ void copy_kernel(const float* __restrict__ src, float* __restrict__ dst, int n){
    int i = blockIdx.x*blockDim.x + threadIdx.x;
    if (i < n) dst[i] = src[i];
}

/* ---------------- in_proj GEMM: out[M=BL][514] = x[M][64] @ W[514][64]^T --- */
__global__ void inproj_kernel(const float* __restrict__ x, const float* __restrict__ W){
    __shared__ float xsT[64][68];   /* [k][m] */
    __shared__ float wsT[64][68];   /* [k][n] */
    int m0 = blockIdx.x * 64;
    int n0 = blockIdx.y * 64;
    int tid = threadIdx.x;
    for (int idx = tid; idx < 64*64; idx += 256){
        int m = idx >> 6, k = idx & 63;
        xsT[k][m] = x[(long)(m0+m)*DM + k];
    }
    for (int idx = tid; idx < 64*64; idx += 256){
        int n = idx >> 6, k = idx & 63;
        wsT[k][n] = (n0+n < DPROJ) ? W[(n0+n)*DM + k] : 0.f;
    }
    __syncthreads();
    int ty = tid >> 4, tx = tid & 15;
    float acc[4][4] = {};
    #pragma unroll
    for (int k = 0; k < 64; k++){
        float4 a  = *(const float4*)&xsT[k][ty*4];
        float4 bv = *(const float4*)&wsT[k][tx*4];
        float av[4] = {a.x,a.y,a.z,a.w};
        float bw[4] = {bv.x,bv.y,bv.z,bv.w};
        #pragma unroll
        for (int i=0;i<4;i++)
            #pragma unroll
            for (int j=0;j<4;j++) acc[i][j] = fmaf(av[i], bw[j], acc[i][j]);
    }
    #pragma unroll
    for (int i=0;i<4;i++){
        long row = m0 + ty*4 + i;
        #pragma unroll
        for (int j=0;j<4;j++){
            int n = n0 + tx*4 + j;
            if (n < DPROJ) g_zxb[row*DPROJ + n] = acc[i][j];
        }
    }
}

/* ---------------- depthwise causal conv (k=4) + SiLU ----------------------- */
__global__ void conv_kernel(const float* __restrict__ cw, const float* __restrict__ cb){
    long i = (long)blockIdx.x*blockDim.x + threadIdx.x;
    if (i >= (long)BL*CONVD) return;
    int  c  = (int)(i % CONVD);
    long bl = i / CONVD;
    int  l  = (int)(bl & (SEQ-1));
    long b  = bl >> 12;
    float acc = cb[c];
    #pragma unroll
    for (int k=0;k<DCONV;k++){
        int ll = l - 3 + k;
        if (ll >= 0)
            acc = fmaf(cw[c*DCONV+k], g_zxb[(b*SEQ+ll)*(long)DPROJ + DI + c], acc);
    }
    g_xbc[i] = siluf(acc);
}

/* ---------------- dt softplus + per-chunk decay cumsum --------------------- */
__global__ void dtprep_kernel(const float* __restrict__ dtb, const float* __restrict__ Alog){
    int g = blockIdx.x*blockDim.x + threadIdx.x;     /* (b,h,c) = 1024 */
    if (g >= BSZ*NH*NC) return;
    int c = g & (NC-1); int h = (g >> 6) & 1; int b = g >> 7;
    float bias = dtb[h];
    float Aneg = -__expf(Alog[h]);
    float accv = 0.f;
    long base = ((long)(b*NH + h))*SEQ + c*QC;
    for (int t=0;t<QC;t++){
        long row = (long)b*SEQ + c*QC + t;
        float raw = g_zxb[row*DPROJ + (DPROJ-NH) + h] + bias;
        float dt = (raw > 20.f) ? raw : log1pf(__expf(raw));
        accv += dt * Aneg;
        g_dt  [base+t] = dt;
        g_lacc[base+t] = accv;
    }
    g_atot[(b*NH+h)*NC + c] = accv;
}

/* ---------------- Phase A: intra-chunk attention + chunk states ------------ */
/* block = (b, chunk), 256 threads. smem layout (floats):
   BsT[128][68], CsT[128][68], Bsn[64][132], Xs[64][132], WsT[64][68],
   la[64], dt[64], cf[64]                                                     */
#define SMA_FLOATS (2*128*68 + 2*64*132 + 64*68 + 192)
__global__ void phaseA_kernel(void){
    int b = blockIdx.x >> 6;
    int c = blockIdx.x & (NC-1);
    int l0 = c*QC;
    extern __shared__ float sm[];
    float* BsT = sm;                    /* [s][t]  */
    float* CsT = BsT + 128*68;          /* [s][t]  */
    float* Bsn = CsT + 128*68;          /* [t][s]  */
    float* Xs  = Bsn + 64*132;          /* [t][p]  */
    float* WsT = Xs  + 64*132;          /* [tp][t] */
    float* la_s = WsT + 64*68;
    float* dt_s = la_s + 64;
    float* cf_s = dt_s + 64;
    int tid = threadIdx.x;

    for (int idx = tid; idx < QC*DS; idx += 256){
        int t = idx >> 7, s = idx & 127;
        long rb = ((long)(b*SEQ + l0 + t))*CONVD;
        float xv = g_xbc[rb + s];
        float bv = g_xbc[rb + DI + s];
        float cv = g_xbc[rb + DI + DS + s];
        Xs [t*132 + s] = xv;
        Bsn[t*132 + s] = bv;
        BsT[s*68 + t]  = bv;
        CsT[s*68 + t]  = cv;
    }
    __syncthreads();

    int ty = tid >> 4, tx = tid & 15;
    /* G[t][tp] = sum_s C[t][s] * B[tp][s] — kept in registers (per thread 4x4) */
    float gacc[4][4] = {};
    for (int s = 0; s < DS; s++){
        float4 a  = *(const float4*)&CsT[s*68 + ty*4];
        float4 bq = *(const float4*)&BsT[s*68 + tx*4];
        float av[4] = {a.x,a.y,a.z,a.w};
        float bw[4] = {bq.x,bq.y,bq.z,bq.w};
        #pragma unroll
        for (int i=0;i<4;i++)
            #pragma unroll
            for (int j=0;j<4;j++) gacc[i][j] = fmaf(av[i], bw[j], gacc[i][j]);
    }

    for (int h = 0; h < NH; h++){
        __syncthreads();                 /* prior-head consumers done */
        if (tid < QC){
            long base = ((long)(b*NH + h))*SEQ + l0 + tid;
            la_s[tid] = g_lacc[base];
            dt_s[tid] = g_dt[base];
        }
        __syncthreads();
        if (tid < QC){
            float at = g_atot[(b*NH+h)*NC + c];
            cf_s[tid] = __expf(at - la_s[tid]) * dt_s[tid];
        }
        /* materialize decayed causal weight matrix (transposed) */
        #pragma unroll
        for (int i=0;i<4;i++){
            int t = ty*4 + i;
            float lat = la_s[t];
            #pragma unroll
            for (int j=0;j<4;j++){
                int tp = tx*4 + j;
                float w = 0.f;
                if (tp <= t) w = __expf(lat - la_s[tp]) * dt_s[tp] * gacc[i][j];
                WsT[tp*68 + t] = w;
            }
        }
        __syncthreads();

        /* Y_intra[t][p] = sum_tp W[t][tp] * X[tp][64h+p] */
        {
            float acc[4][4] = {};
            for (int tp = 0; tp < QC; tp++){
                float4 a  = *(const float4*)&WsT[tp*68 + ty*4];
                float4 b4 = *(const float4*)&Xs [tp*132 + h*HD + tx*4];
                float av[4] = {a.x,a.y,a.z,a.w};
                float bw[4] = {b4.x,b4.y,b4.z,b4.w};
                #pragma unroll
                for (int i=0;i<4;i++)
                    #pragma unroll
                    for (int j=0;j<4;j++) acc[i][j] = fmaf(av[i], bw[j], acc[i][j]);
            }
            #pragma unroll
            for (int i=0;i<4;i++){
                long row = (long)(b*SEQ + l0 + ty*4 + i);
                #pragma unroll
                for (int j=0;j<4;j++)
                    g_y[row*DI + h*HD + tx*4 + j] = acc[i][j];
            }
        }

        /* S[p][s] = sum_t cf[t] * X[t][64h+p] * B[t][s]  (p tile 4, s tile 8) */
        {
            float acc[4][8] = {};
            for (int t = 0; t < QC; t++){
                float cf = cf_s[t];
                float4 a  = *(const float4*)&Xs [t*132 + h*HD + ty*4];
                float4 b0 = *(const float4*)&Bsn[t*132 + tx*8];
                float4 b1 = *(const float4*)&Bsn[t*132 + tx*8 + 4];
                float av[4] = {a.x*cf, a.y*cf, a.z*cf, a.w*cf};
                float bw[8] = {b0.x,b0.y,b0.z,b0.w,b1.x,b1.y,b1.z,b1.w};
                #pragma unroll
                for (int i=0;i<4;i++)
                    #pragma unroll
                    for (int j=0;j<8;j++) acc[i][j] = fmaf(av[i], bw[j], acc[i][j]);
            }
            long base = (((long)((b*NH+h)*NC + c))*HD)*DS;
            #pragma unroll
            for (int i=0;i<4;i++)
                #pragma unroll
                for (int j=0;j<8;j++)
                    g_S[base + (long)(ty*4+i)*DS + tx*8 + j] = acc[i][j];
        }
    }
}

/* ---------------- Phase B: inter-chunk state recurrence -------------------- */
__global__ void phaseB_kernel(void){
    int bh = blockIdx.x;                 /* 16 */
    int tid = threadIdx.x;               /* 256 */
    float h[32];
    #pragma unroll
    for (int i=0;i<32;i++) h[i] = 0.f;
    long base = (long)bh * NC * (HD*DS);
    for (int c=0;c<NC;c++){
        float ea = __expf(g_atot[bh*NC + c]);
        long off = base + (long)c*(HD*DS);
        #pragma unroll
        for (int i=0;i<32;i++){
            int e = tid + i*256;
            g_hst[off + e] = h[i];
            h[i] = fmaf(h[i], ea, g_S[off + e]);
        }
    }
}

/* ---------------- Phase C: inter-chunk output + skip ----------------------- */
#define SMC_FLOATS (128*132 + 128*68 + 128)
__global__ void phaseC_kernel(const float* __restrict__ Dp){
    int b = blockIdx.x >> 6;
    int c = blockIdx.x & (NC-1);
    int l0 = c*QC;
    extern __shared__ float sm[];
    float* hsT  = sm;                   /* [s][pg] pg = 64h+p, stride 132 */
    float* CsT2 = sm + 128*132;         /* [s][t]  stride 68 */
    float* la2  = CsT2 + 128*68;        /* [2][64] */
    int tid = threadIdx.x;

    for (int idx = tid; idx < NH*HD*DS; idx += 256){
        int h = idx >> 13;
        int rem = idx & 8191;
        int p = rem >> 7, s = rem & 127;
        hsT[s*132 + h*HD + p] =
            g_hst[(((long)((b*NH+h)*NC + c))*HD + p)*DS + s];
    }
    for (int idx = tid; idx < QC*DS; idx += 256){
        int t = idx >> 7, s = idx & 127;
        CsT2[s*68 + t] = g_xbc[((long)(b*SEQ+l0+t))*CONVD + DI + DS + s];
    }
    if (tid < NH*QC){
        int h = tid >> 6, t = tid & 63;
        la2[tid] = g_lacc[((long)(b*NH+h))*SEQ + l0 + t];
    }
    __syncthreads();

    int ty = tid >> 4, tx = tid & 15;    /* t tile 4, pg tile 8 */
    float acc[4][8] = {};
    for (int s = 0; s < DS; s++){
        float4 a  = *(const float4*)&CsT2[s*68 + ty*4];
        float4 b0 = *(const float4*)&hsT[s*132 + tx*8];
        float4 b1 = *(const float4*)&hsT[s*132 + tx*8 + 4];
        float av[4] = {a.x,a.y,a.z,a.w};
        float bw[8] = {b0.x,b0.y,b0.z,b0.w,b1.x,b1.y,b1.z,b1.w};
        #pragma unroll
        for (int i=0;i<4;i++)
            #pragma unroll
            for (int j=0;j<8;j++) acc[i][j] = fmaf(av[i], bw[j], acc[i][j]);
    }
    float d0 = Dp[0], d1 = Dp[1];
    #pragma unroll
    for (int i=0;i<4;i++){
        int t = ty*4 + i;
        long row = (long)(b*SEQ + l0 + t);
        #pragma unroll
        for (int j=0;j<8;j++){
            int pg = tx*8 + j;
            int h = pg >> 6;
            float e = __expf(la2[h*64 + t]);
            float xv = g_xbc[row*CONVD + pg];
            float dh = h ? d1 : d0;
            g_y[row*DI + pg] += e*acc[i][j] + dh*xv;
        }
    }
}

/* ---------------- gate * SiLU(z), RMSNorm, out_proj, residual -------------- */
#define SMG_FLOATS (32*132 + 128*68)
__global__ void gateproj_kernel(const float* __restrict__ ow, const float* __restrict__ nw,
                                float* __restrict__ xres){
    extern __shared__ float sm[];
    float* yt  = sm;                    /* [32][132] */
    float* owT = sm + 32*132;           /* [i][m] stride 68 */
    int r0 = blockIdx.x * 32;
    int tid = threadIdx.x;
    for (int idx = tid; idx < DM*DI; idx += 256){
        int m = idx >> 7, i = idx & 127;
        owT[i*68 + m] = ow[idx];
    }
    for (int idx = tid; idx < 32*DI; idx += 256){
        int r = idx >> 7, cc = idx & 127;
        long row = r0 + r;
        float y = g_y  [row*DI + cc];
        float z = g_zxb[row*DPROJ + cc];
        yt[r*132 + cc] = y * siluf(z);
    }
    __syncthreads();
    int wid = tid >> 5, lane = tid & 31;
    for (int r = wid*4; r < wid*4 + 4; r++){
        float s = 0.f;
        for (int cc = lane; cc < DI; cc += 32){ float v = yt[r*132+cc]; s += v*v; }
        #pragma unroll
        for (int o=16;o;o>>=1) s += __shfl_xor_sync(0xffffffffu, s, o);
        float rstd = rsqrtf(s/(float)DI + EPSV);
        for (int cc = lane; cc < DI; cc += 32) yt[r*132+cc] *= rstd * nw[cc];
    }
    __syncthreads();
    int ty = tid >> 4, tx = tid & 15;    /* rows 2, cols 4 */
    float acc[2][4] = {};
    for (int i = 0; i < DI; i++){
        float a0 = yt[(ty*2+0)*132 + i];
        float a1 = yt[(ty*2+1)*132 + i];
        float4 b4 = *(const float4*)&owT[i*68 + tx*4];
        float bw[4] = {b4.x,b4.y,b4.z,b4.w};
        #pragma unroll
        for (int j=0;j<4;j++){
            acc[0][j] = fmaf(a0, bw[j], acc[0][j]);
            acc[1][j] = fmaf(a1, bw[j], acc[1][j]);
        }
    }
    #pragma unroll
    for (int i=0;i<2;i++){
        long row = r0 + ty*2 + i;
        #pragma unroll
        for (int j=0;j<4;j++)
            xres[row*DM + tx*4 + j] += acc[i][j];
    }
}

/* ---------------- host ----------------------------------------------------- */
extern "C" void kernel_launch(void* const* d_in, const int* in_sizes, int n_in,
                              void* d_out, int out_size){
    const float* x     = (const float*)d_in[0];
    const float* inw   = (const float*)d_in[1];
    const float* cw    = (const float*)d_in[2];
    const float* cb    = (const float*)d_in[3];
    const float* dtb   = (const float*)d_in[4];
    const float* alog  = (const float*)d_in[5];
    const float* Dpar  = (const float*)d_in[6];
    const float* nw    = (const float*)d_in[7];
    const float* ow    = (const float*)d_in[8];
    float* out = (float*)d_out;

    static bool attr_done = false;
    cudaFuncSetAttribute(phaseA_kernel,   cudaFuncAttributeMaxDynamicSharedMemorySize, SMA_FLOATS*4);
    cudaFuncSetAttribute(phaseC_kernel,   cudaFuncAttributeMaxDynamicSharedMemorySize, SMC_FLOATS*4);
    cudaFuncSetAttribute(gateproj_kernel, cudaFuncAttributeMaxDynamicSharedMemorySize, SMG_FLOATS*4);
    (void)attr_done;

    int n = BL*DM;
    copy_kernel<<<(n+255)/256, 256>>>(x, out, n);

    for (int layer = 0; layer < NLAYERS; layer++){
        inproj_kernel<<<dim3(BL/64, (DPROJ+63)/64), 256>>>(out, inw + (long)layer*DPROJ*DM);
        long convtot = (long)BL*CONVD;
        conv_kernel<<<(unsigned)((convtot+255)/256), 256>>>(cw + (long)layer*CONVD*DCONV,
                                                            cb + layer*CONVD);
        dtprep_kernel<<<4, 256>>>(dtb + layer*NH, alog + layer*NH);
        phaseA_kernel<<<BSZ*NC, 256, SMA_FLOATS*4>>>();
        phaseB_kernel<<<BSZ*NH, 256>>>();
        phaseC_kernel<<<BSZ*NC, 256, SMC_FLOATS*4>>>(Dpar + layer*NH);
        gateproj_kernel<<<BL/32, 256, SMG_FLOATS*4>>>(ow + (long)layer*DM*DI,
                                                      nw + layer*DI, out);
    }
    (void)in_sizes; (void)n_in; (void)out_size;
}

// round 2
// speedup vs baseline: 1.4746x; 1.4746x over previous
#include <cuda_runtime.h>
#include <math.h>

#define NLAYERS 4
#define DM      64
#define DS      128
#define DCONV   4
#define DI      128
#define NH      2
#define HD      64
#define CONVD   384
#define DZX     512           /* z + xBC columns kept in g_zxb */
#define BSZ     8
#define SEQ     4096
#define BL      (BSZ*SEQ)     /* 32768 */
#define QC      64            /* chunk length */
#define NC      (SEQ/QC)      /* 64 chunks per sequence */
#define EPSV    1e-5f

/* ---------------- scratch (allocation-free: __device__ globals) ------------ */
__device__ float g_zxb [BL*(long)DZX];        /* in_proj output (z,xBC)    */
__device__ float g_xbc [BL*(long)CONVD];      /* post-conv xBC (x,B,C)     */
__device__ float g_dt  [BSZ*NH*SEQ];          /* softplus dt               */
__device__ float g_lacc[BSZ*NH*SEQ];          /* local (per-chunk) cumsum  */
__device__ float g_atot[BSZ*NH*NC];           /* per-chunk total decay     */
__device__ float g_S   [(long)BSZ*NH*NC*HD*DS]; /* chunk state contribution */
__device__ float g_hst [(long)BSZ*NH*NC*HD*DS]; /* state at chunk start     */
__device__ float g_y   [BL*(long)DI];         /* SSM output                */

__device__ __forceinline__ float siluf(float v){ return v / (1.f + __expf(-v)); }

/* ---------------- init: copy x into residual stream (d_out) --------------- */
__global__ void copy_kernel(const float* __restrict__ src, float* __restrict__ dst, int n){
    int i = blockIdx.x*blockDim.x + threadIdx.x;
    if (i < n) dst[i] = src[i];
}

/* ---------------- in_proj GEMM: g_zxb[M=BL][512] = x[M][64] @ W[512][64]^T - */
/* 128x128 block tile, 8x8 per thread (split 4+4), 256 threads               */
__global__ void inproj_kernel(const float* __restrict__ x, const float* __restrict__ W){
    __shared__ float xsT[64*132];   /* [k][m] */
    __shared__ float wsT[64*132];   /* [k][n] */
    int m0 = blockIdx.x * 128;
    int n0 = blockIdx.y * 128;
    int tid = threadIdx.x;
    for (int idx = tid; idx < 128*64; idx += 256){
        int m = idx >> 6, k = idx & 63;
        xsT[k*132 + m] = x[(long)(m0+m)*DM + k];
    }
    for (int idx = tid; idx < 128*64; idx += 256){
        int n = idx >> 6, k = idx & 63;
        wsT[k*132 + n] = W[(n0+n)*DM + k];
    }
    __syncthreads();
    int ty = tid >> 4, tx = tid & 15;
    float acc[8][8] = {};
    #pragma unroll 4
    for (int k = 0; k < 64; k++){
        float av[8], bw[8];
        *(float4*)&av[0] = *(const float4*)&xsT[k*132 + ty*4];
        *(float4*)&av[4] = *(const float4*)&xsT[k*132 + 64 + ty*4];
        *(float4*)&bw[0] = *(const float4*)&wsT[k*132 + tx*4];
        *(float4*)&bw[4] = *(const float4*)&wsT[k*132 + 64 + tx*4];
        #pragma unroll
        for (int i=0;i<8;i++)
            #pragma unroll
            for (int j=0;j<8;j++) acc[i][j] = fmaf(av[i], bw[j], acc[i][j]);
    }
    #pragma unroll
    for (int ri=0;ri<2;ri++)
        #pragma unroll
        for (int i=0;i<4;i++){
            long row = m0 + ri*64 + ty*4 + i;
            #pragma unroll
            for (int cj=0;cj<2;cj++){
                float4 v = make_float4(acc[ri*4+i][cj*4+0], acc[ri*4+i][cj*4+1],
                                       acc[ri*4+i][cj*4+2], acc[ri*4+i][cj*4+3]);
                *(float4*)&g_zxb[row*DZX + n0 + cj*64 + tx*4] = v;
            }
        }
}

/* ---------------- depthwise causal conv (k=4) + SiLU, 4 outputs/thread ----- */
__global__ void conv_kernel(const float* __restrict__ cw, const float* __restrict__ cb){
    long i = (long)blockIdx.x*blockDim.x + threadIdx.x;
    if (i >= (long)(BL/4)*CONVD) return;
    int  c  = (int)(i % CONVD);
    long g  = i / CONVD;
    int  l4 = (int)(g & (SEQ/4 - 1));
    long b  = g >> 10;
    int  l0 = l4*4;
    float w0=cw[c*4], w1=cw[c*4+1], w2=cw[c*4+2], w3=cw[c*4+3];
    float bias = cb[c];
    float v[7];
    #pragma unroll
    for (int k=0;k<7;k++){
        int ll = l0 - 3 + k;
        v[k] = (ll >= 0) ? g_zxb[((long)(b*SEQ+ll))*DZX + DI + c] : 0.f;
    }
    #pragma unroll
    for (int o=0;o<4;o++){
        float acc = bias;
        acc = fmaf(w0, v[o],   acc);
        acc = fmaf(w1, v[o+1], acc);
        acc = fmaf(w2, v[o+2], acc);
        acc = fmaf(w3, v[o+3], acc);
        g_xbc[((long)(b*SEQ+l0+o))*CONVD + c] = siluf(acc);
    }
}

/* ------- dt projection + softplus + per-chunk cumsum (1 warp per chunk) ---- */
__global__ void dtprep_kernel(const float* __restrict__ x, const float* __restrict__ W,
                              const float* __restrict__ dtb, const float* __restrict__ Alog){
    int gw = (blockIdx.x*blockDim.x + threadIdx.x) >> 5;   /* 1024 warps */
    int lane = threadIdx.x & 31;
    if (gw >= BSZ*NH*NC) return;
    int c = gw & (NC-1); int h = (gw >> 6) & 1; int b = gw >> 7;
    float bias = dtb[h];
    float Aneg = -__expf(Alog[h]);
    float wA = W[(DZX+h)*DM + lane];
    float wB = W[(DZX+h)*DM + 32 + lane];
    long rowbase = (long)b*SEQ + c*QC;
    float dt0 = 0.f, dt1 = 0.f;
    for (int t=0;t<QC;t++){
        const float* xr = x + (rowbase+t)*DM;
        float p = fmaf(xr[lane], wA, xr[lane+32]*wB);
        #pragma unroll
        for (int o=16;o;o>>=1) p += __shfl_xor_sync(0xffffffffu, p, o);
        float raw = p + bias;
        float dtv = (raw > 20.f) ? raw : log1pf(__expf(raw));
        if (lane == (t>>1)) { if (t & 1) dt1 = dtv; else dt0 = dtv; }
    }
    /* inclusive scan over 64 values (2 per lane) */
    float pp = (dt0 + dt1) * Aneg;
    float s = pp;
    #pragma unroll
    for (int o=1;o<32;o<<=1){ float v = __shfl_up_sync(0xffffffffu, s, o); if (lane >= o) s += v; }
    float excl = s - pp;
    long base = ((long)(b*NH + h))*SEQ + c*QC + 2*lane;
    g_dt  [base]   = dt0;
    g_dt  [base+1] = dt1;
    g_lacc[base]   = excl + dt0*Aneg;
    g_lacc[base+1] = s;
    if (lane == 31) g_atot[(b*NH+h)*NC + c] = s;
}

/* ---------------- Phase A: intra-chunk attention + chunk states ------------ */
/* smem: R0 = BsT[s][t](128x68) -> Bsn[t][s](64x132); R1 = CsT -> WsT; Xs     */
#define SMA_FLOATS (2*128*68 + 64*132 + 192)
__global__ void phaseA_kernel(void){
    int b = blockIdx.x >> 6;
    int c = blockIdx.x & (NC-1);
    int l0 = c*QC;
    extern __shared__ float sm[];
    float* R0 = sm;                 /* BsT then Bsn */
    float* R1 = sm + 128*68;        /* CsT then WsT */
    float* Xs = sm + 2*128*68;      /* [t][p] stride 132 */
    float* la_s = Xs + 64*132;
    float* dt_s = la_s + 64;
    float* cf_s = dt_s + 64;
    int tid = threadIdx.x;

    for (int idx = tid; idx < QC*DS; idx += 256){
        int t = idx >> 7, s = idx & 127;
        long rb = ((long)(b*SEQ + l0 + t))*CONVD;
        Xs[t*132 + s] = g_xbc[rb + s];
        R0[s*68 + t]  = g_xbc[rb + DI + s];        /* B^T */
        R1[s*68 + t]  = g_xbc[rb + DI + DS + s];   /* C^T */
    }
    __syncthreads();

    int ty = tid >> 4, tx = tid & 15;
    /* G[t][tp] = sum_s C[t][s]*B[tp][s] in registers */
    float gacc[4][4] = {};
    for (int s = 0; s < DS; s++){
        float4 a  = *(const float4*)&R1[s*68 + ty*4];
        float4 bq = *(const float4*)&R0[s*68 + tx*4];
        float av[4] = {a.x,a.y,a.z,a.w};
        float bw[4] = {bq.x,bq.y,bq.z,bq.w};
        #pragma unroll
        for (int i=0;i<4;i++)
            #pragma unroll
            for (int j=0;j<4;j++) gacc[i][j] = fmaf(av[i], bw[j], gacc[i][j]);
    }

    /* in-place transpose of B: BsT (R0, [s][t]) -> Bsn (R0, [t][s]) */
    float breg[32];
    {
        int idx = tid;
        #pragma unroll
        for (int r=0;r<32;r++,idx+=256){
            int t = idx >> 7, s = idx & 127;
            breg[r] = R0[s*68 + t];
        }
    }
    __syncthreads();
    {
        int idx = tid;
        #pragma unroll
        for (int r=0;r<32;r++,idx+=256){
            int t = idx >> 7, s = idx & 127;
            R0[t*132 + s] = breg[r];
        }
    }

    for (int h = 0; h < NH; h++){
        __syncthreads();
        if (tid < QC){
            long base = ((long)(b*NH + h))*SEQ + l0 + tid;
            float la = g_lacc[base];
            float dt = g_dt[base];
            la_s[tid] = la;
            dt_s[tid] = dt;
            cf_s[tid] = __expf(g_atot[(b*NH+h)*NC + c] - la) * dt;
        }
        __syncthreads();
        /* decayed causal weight matrix W^T into R1 */
        #pragma unroll
        for (int i=0;i<4;i++){
            int t = ty*4 + i;
            float lat = la_s[t];
            #pragma unroll
            for (int j=0;j<4;j++){
                int tp = tx*4 + j;
                float w = 0.f;
                if (tp <= t) w = __expf(lat - la_s[tp]) * dt_s[tp] * gacc[i][j];
                R1[tp*68 + t] = w;
            }
        }
        __syncthreads();

        /* Y_intra[t][p] = sum_tp W[t][tp]*X[tp][64h+p] */
        {
            float acc[4][4] = {};
            for (int tp = 0; tp < QC; tp++){
                float4 a  = *(const float4*)&R1[tp*68 + ty*4];
                float4 b4 = *(const float4*)&Xs[tp*132 + h*HD + tx*4];
                float av[4] = {a.x,a.y,a.z,a.w};
                float bw[4] = {b4.x,b4.y,b4.z,b4.w};
                #pragma unroll
                for (int i=0;i<4;i++)
                    #pragma unroll
                    for (int j=0;j<4;j++) acc[i][j] = fmaf(av[i], bw[j], acc[i][j]);
            }
            #pragma unroll
            for (int i=0;i<4;i++){
                long row = (long)(b*SEQ + l0 + ty*4 + i);
                #pragma unroll
                for (int j=0;j<4;j++)
                    g_y[row*DI + h*HD + tx*4 + j] = acc[i][j];
            }
        }

        /* S[p][s] = sum_t cf[t]*X[t][64h+p]*B[t][s] */
        {
            float acc[4][8] = {};
            for (int t = 0; t < QC; t++){
                float cf = cf_s[t];
                float4 a  = *(const float4*)&Xs[t*132 + h*HD + ty*4];
                float4 b0 = *(const float4*)&R0[t*132 + tx*8];
                float4 b1 = *(const float4*)&R0[t*132 + tx*8 + 4];
                float av[4] = {a.x*cf, a.y*cf, a.z*cf, a.w*cf};
                float bw[8] = {b0.x,b0.y,b0.z,b0.w,b1.x,b1.y,b1.z,b1.w};
                #pragma unroll
                for (int i=0;i<4;i++)
                    #pragma unroll
                    for (int j=0;j<8;j++) acc[i][j] = fmaf(av[i], bw[j], acc[i][j]);
            }
            long base = (((long)((b*NH+h)*NC + c))*HD)*DS;
            #pragma unroll
            for (int i=0;i<4;i++)
                #pragma unroll
                for (int j=0;j<8;j++)
                    g_S[base + (long)(ty*4+i)*DS + tx*8 + j] = acc[i][j];
        }
    }
}

/* ---------------- Phase B: inter-chunk recurrence, 128 blocks, prefetch ---- */
__global__ void phaseB_kernel(void){
    __shared__ float ea_s[NC];
    int bh   = blockIdx.x >> 3;
    int part = blockIdx.x & 7;
    int tid  = threadIdx.x;
    if (tid < NC) ea_s[tid] = __expf(g_atot[bh*NC + tid]);
    __syncthreads();
    long ebase = (long)bh*NC*(HD*DS) + part*1024 + tid*4;
    float4 h = make_float4(0.f,0.f,0.f,0.f);
    float4 scur = *(const float4*)&g_S[ebase];
    for (int c = 0; c < NC; c++){
        float4 snext = scur;
        if (c+1 < NC) snext = *(const float4*)&g_S[ebase + (long)(c+1)*(HD*DS)];
        *(float4*)&g_hst[ebase + (long)c*(HD*DS)] = h;
        float ea = ea_s[c];
        h.x = fmaf(h.x, ea, scur.x);
        h.y = fmaf(h.y, ea, scur.y);
        h.z = fmaf(h.z, ea, scur.z);
        h.w = fmaf(h.w, ea, scur.w);
        scur = snext;
    }
}

/* ---------------- Phase C: inter-chunk output + skip ----------------------- */
#define SMC_FLOATS (128*132 + 128*68 + 128)
__global__ void phaseC_kernel(const float* __restrict__ Dp){
    int b = blockIdx.x >> 6;
    int c = blockIdx.x & (NC-1);
    int l0 = c*QC;
    extern __shared__ float sm[];
    float* hsT  = sm;                   /* [s][pg] stride 132 */
    float* CsT2 = sm + 128*132;         /* [s][t]  stride 68  */
    float* la2  = CsT2 + 128*68;        /* [2][64] */
    int tid = threadIdx.x;

    for (int idx = tid; idx < NH*HD*DS; idx += 256){
        int h = idx >> 13;
        int rem = idx & 8191;
        int p = rem >> 7, s = rem & 127;
        hsT[s*132 + h*HD + p] =
            g_hst[(((long)((b*NH+h)*NC + c))*HD + p)*DS + s];
    }
    for (int idx = tid; idx < QC*DS; idx += 256){
        int t = idx >> 7, s = idx & 127;
        CsT2[s*68 + t] = g_xbc[((long)(b*SEQ+l0+t))*CONVD + DI + DS + s];
    }
    if (tid < NH*QC){
        int h = tid >> 6, t = tid & 63;
        la2[tid] = g_lacc[((long)(b*NH+h))*SEQ + l0 + t];
    }
    __syncthreads();

    int ty = tid >> 4, tx = tid & 15;
    float acc[4][8] = {};
    for (int s = 0; s < DS; s++){
        float4 a  = *(const float4*)&CsT2[s*68 + ty*4];
        float4 b0 = *(const float4*)&hsT[s*132 + tx*8];
        float4 b1 = *(const float4*)&hsT[s*132 + tx*8 + 4];
        float av[4] = {a.x,a.y,a.z,a.w};
        float bw[8] = {b0.x,b0.y,b0.z,b0.w,b1.x,b1.y,b1.z,b1.w};
        #pragma unroll
        for (int i=0;i<4;i++)
            #pragma unroll
            for (int j=0;j<8;j++) acc[i][j] = fmaf(av[i], bw[j], acc[i][j]);
    }
    float d0 = Dp[0], d1 = Dp[1];
    #pragma unroll
    for (int i=0;i<4;i++){
        int t = ty*4 + i;
        long row = (long)(b*SEQ + l0 + t);
        #pragma unroll
        for (int j=0;j<8;j++){
            int pg = tx*8 + j;
            int h = pg >> 6;
            float e = __expf(la2[h*64 + t]);
            float xv = g_xbc[row*CONVD + pg];
            float dh = h ? d1 : d0;
            g_y[row*DI + pg] += e*acc[i][j] + dh*xv;
        }
    }
}

/* ---------------- gate * SiLU(z), RMSNorm, out_proj, residual -------------- */
#define SMG_FLOATS (32*132 + 128*68)
__global__ void gateproj_kernel(const float* __restrict__ ow, const float* __restrict__ nw,
                                float* __restrict__ xres){
    extern __shared__ float sm[];
    float* yt  = sm;                    /* [32][132] */
    float* owT = sm + 32*132;           /* [i][m] stride 68 */
    int r0 = blockIdx.x * 32;
    int tid = threadIdx.x;
    for (int idx = tid; idx < DM*DI; idx += 256){
        int m = idx >> 7, i = idx & 127;
        owT[i*68 + m] = ow[idx];
    }
    for (int idx = tid; idx < 32*DI; idx += 256){
        int r = idx >> 7, cc = idx & 127;
        long row = r0 + r;
        float y = g_y  [row*DI + cc];
        float z = g_zxb[row*DZX + cc];
        yt[r*132 + cc] = y * siluf(z);
    }
    __syncthreads();
    int wid = tid >> 5, lane = tid & 31;
    for (int r = wid*4; r < wid*4 + 4; r++){
        float s = 0.f;
        for (int cc = lane; cc < DI; cc += 32){ float v = yt[r*132+cc]; s += v*v; }
        #pragma unroll
        for (int o=16;o;o>>=1) s += __shfl_xor_sync(0xffffffffu, s, o);
        float rstd = rsqrtf(s/(float)DI + EPSV);
        for (int cc = lane; cc < DI; cc += 32) yt[r*132+cc] *= rstd * nw[cc];
    }
    __syncthreads();
    int ty = tid >> 4, tx = tid & 15;
    float acc[2][4] = {};
    for (int i = 0; i < DI; i++){
        float a0 = yt[(ty*2+0)*132 + i];
        float a1 = yt[(ty*2+1)*132 + i];
        float4 b4 = *(const float4*)&owT[i*68 + tx*4];
        float bw[4] = {b4.x,b4.y,b4.z,b4.w};
        #pragma unroll
        for (int j=0;j<4;j++){
            acc[0][j] = fmaf(a0, bw[j], acc[0][j]);
            acc[1][j] = fmaf(a1, bw[j], acc[1][j]);
        }
    }
    #pragma unroll
    for (int i=0;i<2;i++){
        long row = r0 + ty*2 + i;
        #pragma unroll
        for (int j=0;j<4;j++)
            xres[row*DM + tx*4 + j] += acc[i][j];
    }
}

/* ---------------- host ----------------------------------------------------- */
extern "C" void kernel_launch(void* const* d_in, const int* in_sizes, int n_in,
                              void* d_out, int out_size){
    const float* x0    = (const float*)d_in[0];
    const float* inw   = (const float*)d_in[1];
    const float* cw    = (const float*)d_in[2];
    const float* cb    = (const float*)d_in[3];
    const float* dtb   = (const float*)d_in[4];
    const float* alog  = (const float*)d_in[5];
    const float* Dpar  = (const float*)d_in[6];
    const float* nw    = (const float*)d_in[7];
    const float* ow    = (const float*)d_in[8];
    float* out = (float*)d_out;

    cudaFuncSetAttribute(phaseA_kernel,   cudaFuncAttributeMaxDynamicSharedMemorySize, SMA_FLOATS*4);
    cudaFuncSetAttribute(phaseC_kernel,   cudaFuncAttributeMaxDynamicSharedMemorySize, SMC_FLOATS*4);
    cudaFuncSetAttribute(gateproj_kernel, cudaFuncAttributeMaxDynamicSharedMemorySize, SMG_FLOATS*4);

    int n = BL*DM;
    copy_kernel<<<(n+255)/256, 256>>>(x0, out, n);

    const int DPROJ = DZX + NH;   /* per-layer weight row count = 514 */
    for (int layer = 0; layer < NLAYERS; layer++){
        const float* Wl = inw + (long)layer*DPROJ*DM;
        inproj_kernel<<<dim3(BL/128, DZX/128), 256>>>(out, Wl);
        long conv4 = (long)(BL/4)*CONVD;
        conv_kernel<<<(unsigned)((conv4+255)/256), 256>>>(cw + (long)layer*CONVD*DCONV,
                                                          cb + layer*CONVD);
        dtprep_kernel<<<128, 256>>>(out, Wl, dtb + layer*NH, alog + layer*NH);
        phaseA_kernel<<<BSZ*NC, 256, SMA_FLOATS*4>>>();
        phaseB_kernel<<<BSZ*NH*8, 256>>>();
        phaseC_kernel<<<BSZ*NC, 256, SMC_FLOATS*4>>>(Dpar + layer*NH);
        gateproj_kernel<<<BL/32, 256, SMG_FLOATS*4>>>(ow + (long)layer*DM*DI,
                                                      nw + layer*DI, out);
    }
    (void)in_sizes; (void)n_in; (void)out_size;
}

// round 3
// speedup vs baseline: 2.3723x; 1.6088x over previous
#include <cuda_runtime.h>
#include <math.h>

#define NLAYERS 4
#define DM      64
#define DS      128
#define DCONV   4
#define DI      128
#define NH      2
#define HD      64
#define CONVD   384
#define DZX     512           /* z + xBC columns kept in g_zxb */
#define BSZ     8
#define SEQ     4096
#define BL      (BSZ*SEQ)     /* 32768 */
#define QC      64            /* chunk length */
#define NC      (SEQ/QC)      /* 64 chunks per sequence */
#define EPSV    1e-5f

/* ---------------- scratch (allocation-free: __device__ globals) ------------ */
__device__ float g_zxb [BL*(long)DZX];        /* in_proj output (z,xBC)    */
__device__ float g_xbc [BL*(long)CONVD];      /* post-conv x,C (B unused)  */
__device__ float g_dt  [BSZ*NH*SEQ];
__device__ float g_lacc[BSZ*NH*SEQ];
__device__ float g_atot[BSZ*NH*NC];
__device__ float g_S   [(long)BSZ*NH*NC*HD*DS];
__device__ float g_hst [(long)BSZ*NH*NC*HD*DS];
__device__ float g_y   [BL*(long)DI];         /* intra-chunk SSM output    */

__device__ __forceinline__ float siluf(float v){ return v / (1.f + __expf(-v)); }

/* ---------------- init: copy x into residual stream (d_out) --------------- */
__global__ void copy_kernel(const float* __restrict__ src, float* __restrict__ dst, int n4){
    int i = blockIdx.x*blockDim.x + threadIdx.x;
    if (i < n4) ((float4*)dst)[i] = ((const float4*)src)[i];
}

/* ---------------- in_proj GEMM: g_zxb[BL][512] = x[BL][64] @ W[512][64]^T -- */
__global__ void inproj_kernel(const float* __restrict__ x, const float* __restrict__ W){
    __shared__ float xsT[64*132];   /* [k][m] */
    __shared__ float wsT[64*132];   /* [k][n] */
    int m0 = blockIdx.x * 128;
    int n0 = blockIdx.y * 128;
    int tid = threadIdx.x;
    for (int idx = tid; idx < 128*64; idx += 256){
        int m = idx >> 6, k = idx & 63;
        xsT[k*132 + m] = x[(long)(m0+m)*DM + k];
    }
    for (int idx = tid; idx < 128*64; idx += 256){
        int n = idx >> 6, k = idx & 63;
        wsT[k*132 + n] = W[(n0+n)*DM + k];
    }
    __syncthreads();
    int ty = tid >> 4, tx = tid & 15;
    float acc[8][8] = {};
    #pragma unroll 4
    for (int k = 0; k < 64; k++){
        float av[8], bw[8];
        *(float4*)&av[0] = *(const float4*)&xsT[k*132 + ty*4];
        *(float4*)&av[4] = *(const float4*)&xsT[k*132 + 64 + ty*4];
        *(float4*)&bw[0] = *(const float4*)&wsT[k*132 + tx*4];
        *(float4*)&bw[4] = *(const float4*)&wsT[k*132 + 64 + tx*4];
        #pragma unroll
        for (int i=0;i<8;i++)
            #pragma unroll
            for (int j=0;j<8;j++) acc[i][j] = fmaf(av[i], bw[j], acc[i][j]);
    }
    #pragma unroll
    for (int ri=0;ri<2;ri++)
        #pragma unroll
        for (int i=0;i<4;i++){
            long row = m0 + ri*64 + ty*4 + i;
            #pragma unroll
            for (int cj=0;cj<2;cj++){
                float4 v = make_float4(acc[ri*4+i][cj*4+0], acc[ri*4+i][cj*4+1],
                                       acc[ri*4+i][cj*4+2], acc[ri*4+i][cj*4+3]);
                *(float4*)&g_zxb[row*DZX + n0 + cj*64 + tx*4] = v;
            }
        }
}

/* ------- dt: private dot products per lane + warp scan --------------------- */
__global__ void dtprep_kernel(const float* __restrict__ x, const float* __restrict__ W,
                              const float* __restrict__ dtb, const float* __restrict__ Alog){
    int gw = (blockIdx.x*blockDim.x + threadIdx.x) >> 5;   /* 1024 warps */
    int lane = threadIdx.x & 31;
    if (gw >= BSZ*NH*NC) return;
    int c = gw & (NC-1); int h = (gw >> 6) & 1; int b = gw >> 7;
    float bias = dtb[h];
    float Aneg = -__expf(Alog[h]);
    long rowbase = (long)b*SEQ + c*QC;
    const float* xr = x + (rowbase + 2*lane)*DM;
    const float* wr = W + (long)(DZX+h)*DM;
    float raw0 = bias, raw1 = bias;
    #pragma unroll
    for (int k4 = 0; k4 < 16; k4++){
        float4 w  = *(const float4*)&wr[k4*4];
        float4 a  = *(const float4*)&xr[k4*4];
        float4 bq = *(const float4*)&xr[DM + k4*4];
        raw0 = fmaf(a.x,w.x, fmaf(a.y,w.y, fmaf(a.z,w.z, fmaf(a.w,w.w, raw0))));
        raw1 = fmaf(bq.x,w.x, fmaf(bq.y,w.y, fmaf(bq.z,w.z, fmaf(bq.w,w.w, raw1))));
    }
    float dt0 = (raw0 > 20.f) ? raw0 : log1pf(__expf(raw0));
    float dt1 = (raw1 > 20.f) ? raw1 : log1pf(__expf(raw1));
    float pp = (dt0 + dt1) * Aneg;
    float s = pp;
    #pragma unroll
    for (int o=1;o<32;o<<=1){ float v = __shfl_up_sync(0xffffffffu, s, o); if (lane >= o) s += v; }
    float excl = s - pp;
    long base = ((long)(b*NH + h))*SEQ + c*QC + 2*lane;
    g_dt  [base]   = dt0;
    g_dt  [base+1] = dt1;
    g_lacc[base]   = excl + dt0*Aneg;
    g_lacc[base+1] = s;
    if (lane == 31) g_atot[(b*NH+h)*NC + c] = s;
}

/* ---------------- Phase A: fused conv+SiLU, intra-chunk attn, chunk states - */
#define SMA_FLOATS (2*128*68 + 64*132 + 192 + 1536 + 384)
__global__ void phaseA_kernel(const float* __restrict__ cw, const float* __restrict__ cb){
    int b = blockIdx.x >> 6;
    int c = blockIdx.x & (NC-1);
    int l0 = c*QC;
    extern __shared__ float sm[];
    float* R0   = sm;                 /* BsT[s][t] -> Bsn[t][s] */
    float* R1   = sm + 128*68;        /* CsT[s][t] -> WsT[tp][t] */
    float* Xs   = sm + 2*128*68;      /* [t][p] stride 132 */
    float* la_s = Xs + 64*132;
    float* dt_s = la_s + 64;
    float* cf_s = dt_s + 64;
    float* cw_s = cf_s + 64;          /* 1536 */
    float* cb_s = cw_s + 1536;        /* 384  */
    int tid = threadIdx.x;

    for (int i = tid; i < CONVD*DCONV; i += 256) cw_s[i] = cw[i];
    for (int i = tid; i < CONVD; i += 256)       cb_s[i] = cb[i];
    __syncthreads();

    /* fused depthwise conv + SiLU directly from g_zxb */
    for (int idx = tid; idx < QC*CONVD; idx += 256){
        int t  = idx / CONVD;
        int ch = idx - t*CONVD;
        int l  = l0 + t;
        float acc = cb_s[ch];
        #pragma unroll
        for (int k=0;k<DCONV;k++){
            int ll = l - 3 + k;
            if (ll >= 0)
                acc = fmaf(cw_s[ch*4+k], g_zxb[((long)(b*SEQ+ll))*DZX + DI + ch], acc);
        }
        float v = siluf(acc);
        long rowb = (long)(b*SEQ + l);
        if (ch < DI){
            Xs[t*132 + ch] = v;
            g_xbc[rowb*CONVD + ch] = v;
        } else if (ch < DI+DS){
            R0[(ch-DI)*68 + t] = v;                  /* B^T */
        } else {
            R1[(ch-DI-DS)*68 + t] = v;               /* C^T */
            g_xbc[rowb*CONVD + ch] = v;
        }
    }
    __syncthreads();

    int ty = tid >> 4, tx = tid & 15;
    /* G[t][tp] = sum_s C[t][s]*B[tp][s] */
    float gacc[4][4] = {};
    for (int s = 0; s < DS; s++){
        float4 a  = *(const float4*)&R1[s*68 + ty*4];
        float4 bq = *(const float4*)&R0[s*68 + tx*4];
        float av[4] = {a.x,a.y,a.z,a.w};
        float bw[4] = {bq.x,bq.y,bq.z,bq.w};
        #pragma unroll
        for (int i=0;i<4;i++)
            #pragma unroll
            for (int j=0;j<4;j++) gacc[i][j] = fmaf(av[i], bw[j], gacc[i][j]);
    }

    /* in-place transpose of B: [s][t] -> [t][s] */
    float breg[32];
    {
        int idx = tid;
        #pragma unroll
        for (int r=0;r<32;r++,idx+=256){
            int t = idx >> 7, s = idx & 127;
            breg[r] = R0[s*68 + t];
        }
    }
    __syncthreads();
    {
        int idx = tid;
        #pragma unroll
        for (int r=0;r<32;r++,idx+=256){
            int t = idx >> 7, s = idx & 127;
            R0[t*132 + s] = breg[r];
        }
    }

    for (int h = 0; h < NH; h++){
        __syncthreads();
        if (tid < QC){
            long base = ((long)(b*NH + h))*SEQ + l0 + tid;
            float la = g_lacc[base];
            float dt = g_dt[base];
            la_s[tid] = la;
            dt_s[tid] = dt;
            cf_s[tid] = __expf(g_atot[(b*NH+h)*NC + c] - la) * dt;
        }
        __syncthreads();
        #pragma unroll
        for (int i=0;i<4;i++){
            int t = ty*4 + i;
            float lat = la_s[t];
            #pragma unroll
            for (int j=0;j<4;j++){
                int tp = tx*4 + j;
                float w = 0.f;
                if (tp <= t) w = __expf(lat - la_s[tp]) * dt_s[tp] * gacc[i][j];
                R1[tp*68 + t] = w;
            }
        }
        __syncthreads();

        /* Y_intra */
        {
            float acc[4][4] = {};
            for (int tp = 0; tp < QC; tp++){
                float4 a  = *(const float4*)&R1[tp*68 + ty*4];
                float4 b4 = *(const float4*)&Xs[tp*132 + h*HD + tx*4];
                float av[4] = {a.x,a.y,a.z,a.w};
                float bw[4] = {b4.x,b4.y,b4.z,b4.w};
                #pragma unroll
                for (int i=0;i<4;i++)
                    #pragma unroll
                    for (int j=0;j<4;j++) acc[i][j] = fmaf(av[i], bw[j], acc[i][j]);
            }
            #pragma unroll
            for (int i=0;i<4;i++){
                long row = (long)(b*SEQ + l0 + ty*4 + i);
                #pragma unroll
                for (int j=0;j<4;j++)
                    g_y[row*DI + h*HD + tx*4 + j] = acc[i][j];
            }
        }

        /* S[p][s] */
        {
            float acc[4][8] = {};
            for (int t = 0; t < QC; t++){
                float cf = cf_s[t];
                float4 a  = *(const float4*)&Xs[t*132 + h*HD + ty*4];
                float4 b0 = *(const float4*)&R0[t*132 + tx*8];
                float4 b1 = *(const float4*)&R0[t*132 + tx*8 + 4];
                float av[4] = {a.x*cf, a.y*cf, a.z*cf, a.w*cf};
                float bw[8] = {b0.x,b0.y,b0.z,b0.w,b1.x,b1.y,b1.z,b1.w};
                #pragma unroll
                for (int i=0;i<4;i++)
                    #pragma unroll
                    for (int j=0;j<8;j++) acc[i][j] = fmaf(av[i], bw[j], acc[i][j]);
            }
            long base = (((long)((b*NH+h)*NC + c))*HD)*DS;
            #pragma unroll
            for (int i=0;i<4;i++)
                #pragma unroll
                for (int j=0;j<8;j++)
                    g_S[base + (long)(ty*4+i)*DS + tx*8 + j] = acc[i][j];
        }
    }
}

/* ---------------- Phase B: inter-chunk recurrence -------------------------- */
__global__ void phaseB_kernel(void){
    __shared__ float ea_s[NC];
    int bh   = blockIdx.x >> 3;
    int part = blockIdx.x & 7;
    int tid  = threadIdx.x;
    if (tid < NC) ea_s[tid] = __expf(g_atot[bh*NC + tid]);
    __syncthreads();
    long ebase = (long)bh*NC*(HD*DS) + part*1024 + tid*4;
    float4 h = make_float4(0.f,0.f,0.f,0.f);
    float4 scur = *(const float4*)&g_S[ebase];
    for (int c = 0; c < NC; c++){
        float4 snext = scur;
        if (c+1 < NC) snext = *(const float4*)&g_S[ebase + (long)(c+1)*(HD*DS)];
        *(float4*)&g_hst[ebase + (long)c*(HD*DS)] = h;
        float ea = ea_s[c];
        h.x = fmaf(h.x, ea, scur.x);
        h.y = fmaf(h.y, ea, scur.y);
        h.z = fmaf(h.z, ea, scur.z);
        h.w = fmaf(h.w, ea, scur.w);
        scur = snext;
    }
}

/* ------ Phase C+G: inter-chunk out, skip, gate, RMSNorm, out_proj, resid --- */
#define SMCG_FLOATS (128*68 + 128*68 + 64*132 + 128)
__global__ void phaseCG_kernel(const float* __restrict__ Dp, const float* __restrict__ ow,
                               const float* __restrict__ nw, float* __restrict__ xres){
    int b = blockIdx.x >> 6;
    int c = blockIdx.x & (NC-1);
    int l0 = c*QC;
    extern __shared__ float sm[];
    float* CsT2 = sm;                 /* [s][t] stride 68; later owT [i][m] */
    float* hsT  = sm + 128*68;        /* [s][p] stride 68, per head */
    float* yt   = sm + 2*128*68;      /* [t][pg] stride 132 */
    float* la2  = yt + 64*132;        /* [2][64] */
    int tid = threadIdx.x;

    for (int idx = tid; idx < QC*DS; idx += 256){
        int t = idx >> 7, s = idx & 127;
        CsT2[s*68 + t] = g_xbc[((long)(b*SEQ+l0+t))*CONVD + DI + DS + s];
    }
    if (tid < NH*QC){
        int h = tid >> 6, t = tid & 63;
        la2[tid] = g_lacc[((long)(b*NH+h))*SEQ + l0 + t];
    }
    int ty = tid >> 4, tx = tid & 15;
    float d0 = Dp[0], d1 = Dp[1];

    for (int h = 0; h < NH; h++){
        __syncthreads();
        for (int idx = tid; idx < HD*DS; idx += 256){
            int p = idx >> 7, s = idx & 127;
            hsT[s*68 + p] = g_hst[(((long)((b*NH+h)*NC + c))*HD + p)*DS + s];
        }
        __syncthreads();
        float acc[4][4] = {};
        for (int s = 0; s < DS; s++){
            float4 a  = *(const float4*)&CsT2[s*68 + ty*4];
            float4 b4 = *(const float4*)&hsT[s*68 + tx*4];
            float av[4] = {a.x,a.y,a.z,a.w};
            float bw[4] = {b4.x,b4.y,b4.z,b4.w};
            #pragma unroll
            for (int i=0;i<4;i++)
                #pragma unroll
                for (int j=0;j<4;j++) acc[i][j] = fmaf(av[i], bw[j], acc[i][j]);
        }
        float dh = h ? d1 : d0;
        #pragma unroll
        for (int i=0;i<4;i++){
            int t = ty*4 + i;
            long row = (long)(b*SEQ + l0 + t);
            float e = __expf(la2[h*64 + t]);
            #pragma unroll
            for (int j=0;j<4;j++){
                int pg = h*HD + tx*4 + j;
                float xv = g_xbc[row*CONVD + pg];
                float y  = g_y[row*DI + pg] + e*acc[i][j] + dh*xv;
                float z  = g_zxb[row*DZX + pg];
                yt[t*132 + pg] = y * siluf(z);
            }
        }
    }
    __syncthreads();

    /* owT overwrites CsT2 region */
    for (int idx = tid; idx < DM*DI; idx += 256){
        int m = idx >> 7, i = idx & 127;
        CsT2[i*68 + m] = ow[idx];
    }
    /* RMSNorm: 8 warps x 8 rows */
    int wid = tid >> 5, lane = tid & 31;
    for (int r = wid*8; r < wid*8 + 8; r++){
        float s = 0.f;
        #pragma unroll
        for (int q=0;q<4;q++){ float v = yt[r*132 + lane + q*32]; s += v*v; }
        #pragma unroll
        for (int o=16;o;o>>=1) s += __shfl_xor_sync(0xffffffffu, s, o);
        float rstd = rsqrtf(s/(float)DI + EPSV);
        #pragma unroll
        for (int q=0;q<4;q++){
            int cc = lane + q*32;
            yt[r*132 + cc] *= rstd * __ldg(&nw[cc]);
        }
    }
    __syncthreads();

    /* out_proj 64x64 + residual */
    float acc2[4][4] = {};
    for (int k = 0; k < DI; k++){
        float av[4];
        #pragma unroll
        for (int r=0;r<4;r++) av[r] = yt[(ty*4+r)*132 + k];
        float4 b4 = *(const float4*)&CsT2[k*68 + tx*4];
        float bw[4] = {b4.x,b4.y,b4.z,b4.w};
        #pragma unroll
        for (int i=0;i<4;i++)
            #pragma unroll
            for (int j=0;j<4;j++) acc2[i][j] = fmaf(av[i], bw[j], acc2[i][j]);
    }
    #pragma unroll
    for (int i=0;i<4;i++){
        long row = (long)(b*SEQ + l0 + ty*4 + i);
        float4 old = *(float4*)&xres[row*DM + tx*4];
        old.x += acc2[i][0]; old.y += acc2[i][1];
        old.z += acc2[i][2]; old.w += acc2[i][3];
        *(float4*)&xres[row*DM + tx*4] = old;
    }
}

/* ---------------- host ----------------------------------------------------- */
extern "C" void kernel_launch(void* const* d_in, const int* in_sizes, int n_in,
                              void* d_out, int out_size){
    const float* x0    = (const float*)d_in[0];
    const float* inw   = (const float*)d_in[1];
    const float* cw    = (const float*)d_in[2];
    const float* cb    = (const float*)d_in[3];
    const float* dtb   = (const float*)d_in[4];
    const float* alog  = (const float*)d_in[5];
    const float* Dpar  = (const float*)d_in[6];
    const float* nw    = (const float*)d_in[7];
    const float* ow    = (const float*)d_in[8];
    float* out = (float*)d_out;

    cudaFuncSetAttribute(phaseA_kernel,  cudaFuncAttributeMaxDynamicSharedMemorySize, SMA_FLOATS*4);
    cudaFuncSetAttribute(phaseCG_kernel, cudaFuncAttributeMaxDynamicSharedMemorySize, SMCG_FLOATS*4);

    copy_kernel<<<(BL*DM/4+255)/256, 256>>>(x0, out, BL*DM/4);

    const int DPROJ = DZX + NH;
    for (int layer = 0; layer < NLAYERS; layer++){
        const float* Wl = inw + (long)layer*DPROJ*DM;
        inproj_kernel<<<dim3(BL/128, DZX/128), 256>>>(out, Wl);
        dtprep_kernel<<<128, 256>>>(out, Wl, dtb + layer*NH, alog + layer*NH);
        phaseA_kernel<<<BSZ*NC, 256, SMA_FLOATS*4>>>(cw + (long)layer*CONVD*DCONV,
                                                     cb + layer*CONVD);
        phaseB_kernel<<<BSZ*NH*8, 256>>>();
        phaseCG_kernel<<<BSZ*NC, 256, SMCG_FLOATS*4>>>(Dpar + layer*NH,
                                                       ow + (long)layer*DM*DI,
                                                       nw + layer*DI, out);
    }
    (void)in_sizes; (void)n_in; (void)out_size;
}

// round 4
// speedup vs baseline: 2.5054x; 1.0561x over previous
#include <cuda_runtime.h>
#include <math.h>

#define NLAYERS 4
#define DM      64
#define DS      128
#define DCONV   4
#define DI      128
#define NH      2
#define HD      64
#define CONVD   384
#define DZX     512
#define BSZ     8
#define SEQ     4096
#define BL      (BSZ*SEQ)
#define QC      64
#define NC      (SEQ/QC)
#define EPSV    1e-5f

__device__ float g_zxb [BL*(long)DZX];
__device__ float g_xbc [BL*(long)CONVD];      /* x and C parts used */
__device__ float g_dt  [BSZ*NH*SEQ];
__device__ float g_lacc[BSZ*NH*SEQ];
__device__ float g_atot[BSZ*NH*NC];
__device__ float g_S   [(long)BSZ*NH*NC*HD*DS];
__device__ float g_hst [(long)BSZ*NH*NC*HD*DS];
__device__ float g_y   [BL*(long)DI];

__device__ __forceinline__ float siluf(float v){ return v / (1.f + __expf(-v)); }

__global__ void copy_kernel(const float* __restrict__ src, float* __restrict__ dst, int n4){
    int i = blockIdx.x*blockDim.x + threadIdx.x;
    if (i < n4) ((float4*)dst)[i] = ((const float4*)src)[i];
}

/* ---------------- in_proj GEMM ------------------------------------------- */
__global__ void inproj_kernel(const float* __restrict__ x, const float* __restrict__ W){
    __shared__ float xsT[64*132];
    __shared__ float wsT[64*132];
    int m0 = blockIdx.x * 128;
    int n0 = blockIdx.y * 128;
    int tid = threadIdx.x;
    for (int idx = tid; idx < 128*64; idx += 256){
        int m = idx >> 6, k = idx & 63;
        xsT[k*132 + m] = x[(long)(m0+m)*DM + k];
    }
    for (int idx = tid; idx < 128*64; idx += 256){
        int n = idx >> 6, k = idx & 63;
        wsT[k*132 + n] = W[(n0+n)*DM + k];
    }
    __syncthreads();
    int ty = tid >> 4, tx = tid & 15;
    float acc[8][8] = {};
    #pragma unroll 4
    for (int k = 0; k < 64; k++){
        float av[8], bw[8];
        *(float4*)&av[0] = *(const float4*)&xsT[k*132 + ty*4];
        *(float4*)&av[4] = *(const float4*)&xsT[k*132 + 64 + ty*4];
        *(float4*)&bw[0] = *(const float4*)&wsT[k*132 + tx*4];
        *(float4*)&bw[4] = *(const float4*)&wsT[k*132 + 64 + tx*4];
        #pragma unroll
        for (int i=0;i<8;i++)
            #pragma unroll
            for (int j=0;j<8;j++) acc[i][j] = fmaf(av[i], bw[j], acc[i][j]);
    }
    #pragma unroll
    for (int ri=0;ri<2;ri++)
        #pragma unroll
        for (int i=0;i<4;i++){
            long row = m0 + ri*64 + ty*4 + i;
            #pragma unroll
            for (int cj=0;cj<2;cj++){
                float4 v = make_float4(acc[ri*4+i][cj*4+0], acc[ri*4+i][cj*4+1],
                                       acc[ri*4+i][cj*4+2], acc[ri*4+i][cj*4+3]);
                *(float4*)&g_zxb[row*DZX + n0 + cj*64 + tx*4] = v;
            }
        }
}

/* ---------------- dt projection + softplus + chunk scan ------------------- */
__global__ void dtprep_kernel(const float* __restrict__ x, const float* __restrict__ W,
                              const float* __restrict__ dtb, const float* __restrict__ Alog){
    int gw = (blockIdx.x*blockDim.x + threadIdx.x) >> 5;
    int lane = threadIdx.x & 31;
    if (gw >= BSZ*NH*NC) return;
    int c = gw & (NC-1); int h = (gw >> 6) & 1; int b = gw >> 7;
    float bias = dtb[h];
    float Aneg = -__expf(Alog[h]);
    long rowbase = (long)b*SEQ + c*QC;
    const float* xr = x + (rowbase + 2*lane)*DM;
    const float* wr = W + (long)(DZX+h)*DM;
    float raw0 = bias, raw1 = bias;
    #pragma unroll
    for (int k4 = 0; k4 < 16; k4++){
        float4 w  = *(const float4*)&wr[k4*4];
        float4 a  = *(const float4*)&xr[k4*4];
        float4 bq = *(const float4*)&xr[DM + k4*4];
        raw0 = fmaf(a.x,w.x, fmaf(a.y,w.y, fmaf(a.z,w.z, fmaf(a.w,w.w, raw0))));
        raw1 = fmaf(bq.x,w.x, fmaf(bq.y,w.y, fmaf(bq.z,w.z, fmaf(bq.w,w.w, raw1))));
    }
    float dt0 = (raw0 > 20.f) ? raw0 : log1pf(__expf(raw0));
    float dt1 = (raw1 > 20.f) ? raw1 : log1pf(__expf(raw1));
    float pp = (dt0 + dt1) * Aneg;
    float s = pp;
    #pragma unroll
    for (int o=1;o<32;o<<=1){ float v = __shfl_up_sync(0xffffffffu, s, o); if (lane >= o) s += v; }
    float excl = s - pp;
    long base = ((long)(b*NH + h))*SEQ + c*QC + 2*lane;
    g_dt  [base]   = dt0;
    g_dt  [base+1] = dt1;
    g_lacc[base]   = excl + dt0*Aneg;
    g_lacc[base+1] = s;
    if (lane == 31) g_atot[(b*NH+h)*NC + c] = s;
}

/* ---------------- Phase A: conv+SiLU, intra-chunk attn, chunk states ------- */
/* R0: B^T[s][t](128x68) -> Bsn[t][s](64x132)
   R1: C^T[s][t](128x68) -> W both heads [(h*64+tp)][t](128x68)
   Xs: [t][p](64x132); la/dt/cf both heads [128] each                          */
#define SMA_FLOATS (2*128*68 + 64*132 + 3*128)
__global__ void phaseA_kernel(const float* __restrict__ cw, const float* __restrict__ cb){
    int b = blockIdx.x >> 6;
    int c = blockIdx.x & (NC-1);
    int l0 = c*QC;
    extern __shared__ float sm[];
    float* R0   = sm;
    float* R1   = sm + 128*68;
    float* Xs   = sm + 2*128*68;
    float* la_s = Xs + 64*132;     /* [h*64+t] */
    float* dt_s = la_s + 128;
    float* cf_s = dt_s + 128;
    int tid = threadIdx.x;

    /* fused depthwise conv + SiLU from g_zxb */
    for (int idx = tid; idx < QC*CONVD; idx += 256){
        int t  = idx / CONVD;
        int ch = idx - t*CONVD;
        int l  = l0 + t;
        float acc = __ldg(&cb[ch]);
        #pragma unroll
        for (int k=0;k<DCONV;k++){
            int ll = l - 3 + k;
            if (ll >= 0)
                acc = fmaf(__ldg(&cw[ch*4+k]), g_zxb[((long)(b*SEQ+ll))*DZX + DI + ch], acc);
        }
        float v = siluf(acc);
        long rowb = (long)(b*SEQ + l);
        if (ch < DI){
            Xs[t*132 + ch] = v;
            g_xbc[rowb*CONVD + ch] = v;
        } else if (ch < DI+DS){
            R0[(ch-DI)*68 + t] = v;
        } else {
            R1[(ch-DI-DS)*68 + t] = v;
            g_xbc[rowb*CONVD + ch] = v;
        }
    }
    if (tid < NH*QC){
        int h = tid >> 6, t = tid & 63;
        long base = ((long)(b*NH + h))*SEQ + l0 + t;
        float la = g_lacc[base];
        float dt = g_dt[base];
        la_s[tid] = la;
        dt_s[tid] = dt;
        cf_s[tid] = __expf(g_atot[(b*NH+h)*NC + c] - la) * dt;
    }
    __syncthreads();

    int ty = tid >> 4, tx = tid & 15;
    /* G[t][tp] = sum_s C[t][s]*B[tp][s] */
    float gacc[4][4] = {};
    for (int s = 0; s < DS; s++){
        float4 a  = *(const float4*)&R1[s*68 + ty*4];
        float4 bq = *(const float4*)&R0[s*68 + tx*4];
        float av[4] = {a.x,a.y,a.z,a.w};
        float bw[4] = {bq.x,bq.y,bq.z,bq.w};
        #pragma unroll
        for (int i=0;i<4;i++)
            #pragma unroll
            for (int j=0;j<4;j++) gacc[i][j] = fmaf(av[i], bw[j], gacc[i][j]);
    }
    /* stage B for transpose */
    float breg[32];
    {
        int idx = tid;
        #pragma unroll
        for (int r=0;r<32;r++,idx+=256){
            int t = idx >> 7, s = idx & 127;
            breg[r] = R0[s*68 + t];
        }
    }
    __syncthreads();

    /* transpose B into R0[t][s]; build both heads' W into R1 */
    {
        int idx = tid;
        #pragma unroll
        for (int r=0;r<32;r++,idx+=256){
            int t = idx >> 7, s = idx & 127;
            R0[t*132 + s] = breg[r];
        }
    }
    #pragma unroll
    for (int h=0;h<NH;h++){
        #pragma unroll
        for (int i=0;i<4;i++){
            int t = ty*4 + i;
            float lat = la_s[h*64 + t];
            #pragma unroll
            for (int j=0;j<4;j++){
                int tp = tx*4 + j;
                float w = 0.f;
                if (tp <= t) w = __expf(lat - la_s[h*64+tp]) * dt_s[h*64+tp] * gacc[i][j];
                R1[(h*64+tp)*68 + t] = w;
            }
        }
    }
    __syncthreads();

    /* fused Y GEMM: Y[t][pg] = sum_tp W_h[t][tp]*X[tp][pg], h = pg>>6 */
    {
        int h = tx >> 3;
        float acc[4][8] = {};
        for (int tp = 0; tp < QC; tp++){
            float4 a = *(const float4*)&R1[(h*64+tp)*68 + ty*4];
            float4 b0 = *(const float4*)&Xs[tp*132 + tx*8];
            float4 b1 = *(const float4*)&Xs[tp*132 + tx*8 + 4];
            float av[4] = {a.x,a.y,a.z,a.w};
            float bw[8] = {b0.x,b0.y,b0.z,b0.w,b1.x,b1.y,b1.z,b1.w};
            #pragma unroll
            for (int i=0;i<4;i++)
                #pragma unroll
                for (int j=0;j<8;j++) acc[i][j] = fmaf(av[i], bw[j], acc[i][j]);
        }
        #pragma unroll
        for (int i=0;i<4;i++){
            long row = (long)(b*SEQ + l0 + ty*4 + i);
            float4 v0 = make_float4(acc[i][0],acc[i][1],acc[i][2],acc[i][3]);
            float4 v1 = make_float4(acc[i][4],acc[i][5],acc[i][6],acc[i][7]);
            *(float4*)&g_y[row*DI + tx*8]     = v0;
            *(float4*)&g_y[row*DI + tx*8 + 4] = v1;
        }
    }

    /* fused S GEMM: S[pg][s] = sum_t cf_h[t]*X[t][pg]*B[t][s], h = pg>>6 */
    {
        int h = ty >> 3;
        float acc[8][8] = {};
        for (int t = 0; t < QC; t++){
            float cf = cf_s[h*64 + t];
            float4 a0 = *(const float4*)&Xs[t*132 + ty*8];
            float4 a1 = *(const float4*)&Xs[t*132 + ty*8 + 4];
            float4 b0 = *(const float4*)&R0[t*132 + tx*8];
            float4 b1 = *(const float4*)&R0[t*132 + tx*8 + 4];
            float av[8] = {a0.x*cf,a0.y*cf,a0.z*cf,a0.w*cf,a1.x*cf,a1.y*cf,a1.z*cf,a1.w*cf};
            float bw[8] = {b0.x,b0.y,b0.z,b0.w,b1.x,b1.y,b1.z,b1.w};
            #pragma unroll
            for (int i=0;i<8;i++)
                #pragma unroll
                for (int j=0;j<8;j++) acc[i][j] = fmaf(av[i], bw[j], acc[i][j]);
        }
        long base = (((long)((b*NH+h)*NC + c))*HD)*DS;
        #pragma unroll
        for (int i=0;i<8;i++){
            int p = (ty&7)*8 + i;
            float4 v0 = make_float4(acc[i][0],acc[i][1],acc[i][2],acc[i][3]);
            float4 v1 = make_float4(acc[i][4],acc[i][5],acc[i][6],acc[i][7]);
            *(float4*)&g_S[base + (long)p*DS + tx*8]     = v0;
            *(float4*)&g_S[base + (long)p*DS + tx*8 + 4] = v1;
        }
    }
}

/* ---------------- Phase B: inter-chunk recurrence -------------------------- */
__global__ void phaseB_kernel(void){
    __shared__ float ea_s[NC];
    int bh   = blockIdx.x >> 3;
    int part = blockIdx.x & 7;
    int tid  = threadIdx.x;
    if (tid < NC) ea_s[tid] = __expf(g_atot[bh*NC + tid]);
    __syncthreads();
    long ebase = (long)bh*NC*(HD*DS) + part*1024 + tid*4;
    float4 h = make_float4(0.f,0.f,0.f,0.f);
    float4 scur = *(const float4*)&g_S[ebase];
    for (int c = 0; c < NC; c++){
        float4 snext = scur;
        if (c+1 < NC) snext = *(const float4*)&g_S[ebase + (long)(c+1)*(HD*DS)];
        *(float4*)&g_hst[ebase + (long)c*(HD*DS)] = h;
        float ea = ea_s[c];
        h.x = fmaf(h.x, ea, scur.x);
        h.y = fmaf(h.y, ea, scur.y);
        h.z = fmaf(h.z, ea, scur.z);
        h.w = fmaf(h.w, ea, scur.w);
        scur = snext;
    }
}

/* ------ Phase C+G: fused inter-chunk out, gate, RMSNorm, out_proj, resid --- */
/* CsT2 [s][t](128x68) later owT [k][m](128x68); hsT2 [s][pg](128x132) later
   yt [t][pg](64x132); la2 [128]                                               */
#define SMCG_FLOATS (128*68 + 128*132 + 128)
__global__ void phaseCG_kernel(const float* __restrict__ Dp, const float* __restrict__ ow,
                               const float* __restrict__ nw, float* __restrict__ xres){
    int b = blockIdx.x >> 6;
    int c = blockIdx.x & (NC-1);
    int l0 = c*QC;
    extern __shared__ float sm[];
    float* CsT2 = sm;
    float* hsT2 = sm + 128*68;
    float* yt   = hsT2;             /* alias, used after GEMM */
    float* la2  = sm + 128*68 + 128*132;
    int tid = threadIdx.x;

    for (int idx = tid; idx < QC*DS; idx += 256){
        int t = idx >> 7, s = idx & 127;
        CsT2[s*68 + t] = g_xbc[((long)(b*SEQ+l0+t))*CONVD + DI + DS + s];
    }
    for (int idx = tid; idx < DS*NH*HD; idx += 256){
        int s = idx & 127, pg = idx >> 7;
        int h = pg >> 6, p = pg & 63;
        hsT2[s*132 + pg] = g_hst[(((long)((b*NH+h)*NC + c))*HD + p)*DS + s];
    }
    if (tid < NH*QC){
        int h = tid >> 6, t = tid & 63;
        la2[tid] = g_lacc[((long)(b*NH+h))*SEQ + l0 + t];
    }
    __syncthreads();

    int ty = tid >> 4, tx = tid & 15;
    int h = tx >> 3;
    /* Yc[t][pg] = sum_s C[t][s]*h[pg][s] */
    float acc[4][8] = {};
    for (int s = 0; s < DS; s++){
        float4 a  = *(const float4*)&CsT2[s*68 + ty*4];
        float4 b0 = *(const float4*)&hsT2[s*132 + tx*8];
        float4 b1 = *(const float4*)&hsT2[s*132 + tx*8 + 4];
        float av[4] = {a.x,a.y,a.z,a.w};
        float bw[8] = {b0.x,b0.y,b0.z,b0.w,b1.x,b1.y,b1.z,b1.w};
        #pragma unroll
        for (int i=0;i<4;i++)
            #pragma unroll
            for (int j=0;j<8;j++) acc[i][j] = fmaf(av[i], bw[j], acc[i][j]);
    }
    float dh = Dp[h];
    /* epilogue into registers */
    float gated[4][8];
    #pragma unroll
    for (int i=0;i<4;i++){
        int t = ty*4 + i;
        long row = (long)(b*SEQ + l0 + t);
        float e = __expf(la2[h*64 + t]);
        float4 y0 = *(const float4*)&g_y[row*DI + tx*8];
        float4 y1 = *(const float4*)&g_y[row*DI + tx*8 + 4];
        float4 x0 = *(const float4*)&g_xbc[row*CONVD + tx*8];
        float4 x1 = *(const float4*)&g_xbc[row*CONVD + tx*8 + 4];
        float4 z0 = *(const float4*)&g_zxb[row*DZX + tx*8];
        float4 z1 = *(const float4*)&g_zxb[row*DZX + tx*8 + 4];
        float yv[8] = {y0.x,y0.y,y0.z,y0.w,y1.x,y1.y,y1.z,y1.w};
        float xv[8] = {x0.x,x0.y,x0.z,x0.w,x1.x,x1.y,x1.z,x1.w};
        float zv[8] = {z0.x,z0.y,z0.z,z0.w,z1.x,z1.y,z1.z,z1.w};
        #pragma unroll
        for (int j=0;j<8;j++){
            float y = yv[j] + e*acc[i][j] + dh*xv[j];
            gated[i][j] = y * siluf(zv[j]);
        }
    }
    __syncthreads();   /* hsT2 fully consumed -> becomes yt */

    #pragma unroll
    for (int i=0;i<4;i++){
        int t = ty*4 + i;
        *(float4*)&yt[t*132 + tx*8]     = make_float4(gated[i][0],gated[i][1],gated[i][2],gated[i][3]);
        *(float4*)&yt[t*132 + tx*8 + 4] = make_float4(gated[i][4],gated[i][5],gated[i][6],gated[i][7]);
    }
    /* stage out_proj weights over CsT2 */
    for (int idx = tid; idx < DM*DI; idx += 256){
        int m = idx >> 7, k = idx & 127;
        CsT2[k*68 + m] = ow[idx];
    }
    __syncthreads();

    /* RMSNorm: 8 warps x 8 rows */
    int wid = tid >> 5, lane = tid & 31;
    for (int r = wid*8; r < wid*8 + 8; r++){
        float s = 0.f;
        #pragma unroll
        for (int q=0;q<4;q++){ float v = yt[r*132 + lane + q*32]; s += v*v; }
        #pragma unroll
        for (int o=16;o;o>>=1) s += __shfl_xor_sync(0xffffffffu, s, o);
        float rstd = rsqrtf(s/(float)DI + EPSV);
        #pragma unroll
        for (int q=0;q<4;q++){
            int cc = lane + q*32;
            yt[r*132 + cc] *= rstd * __ldg(&nw[cc]);
        }
    }
    __syncthreads();

    /* out_proj 64x64 + residual */
    float acc2[4][4] = {};
    for (int k = 0; k < DI; k++){
        float av[4];
        #pragma unroll
        for (int r=0;r<4;r++) av[r] = yt[(ty*4+r)*132 + k];
        float4 b4 = *(const float4*)&CsT2[k*68 + tx*4];
        float bw[4] = {b4.x,b4.y,b4.z,b4.w};
        #pragma unroll
        for (int i=0;i<4;i++)
            #pragma unroll
            for (int j=0;j<4;j++) acc2[i][j] = fmaf(av[i], bw[j], acc2[i][j]);
    }
    #pragma unroll
    for (int i=0;i<4;i++){
        long row = (long)(b*SEQ + l0 + ty*4 + i);
        float4 old = *(float4*)&xres[row*DM + tx*4];
        old.x += acc2[i][0]; old.y += acc2[i][1];
        old.z += acc2[i][2]; old.w += acc2[i][3];
        *(float4*)&xres[row*DM + tx*4] = old;
    }
}

/* ---------------- host ----------------------------------------------------- */
extern "C" void kernel_launch(void* const* d_in, const int* in_sizes, int n_in,
                              void* d_out, int out_size){
    const float* x0    = (const float*)d_in[0];
    const float* inw   = (const float*)d_in[1];
    const float* cw    = (const float*)d_in[2];
    const float* cb    = (const float*)d_in[3];
    const float* dtb   = (const float*)d_in[4];
    const float* alog  = (const float*)d_in[5];
    const float* Dpar  = (const float*)d_in[6];
    const float* nw    = (const float*)d_in[7];
    const float* ow    = (const float*)d_in[8];
    float* out = (float*)d_out;

    cudaFuncSetAttribute(phaseA_kernel,  cudaFuncAttributeMaxDynamicSharedMemorySize, SMA_FLOATS*4);
    cudaFuncSetAttribute(phaseCG_kernel, cudaFuncAttributeMaxDynamicSharedMemorySize, SMCG_FLOATS*4);

    copy_kernel<<<(BL*DM/4+255)/256, 256>>>(x0, out, BL*DM/4);

    const int DPROJ = DZX + NH;
    for (int layer = 0; layer < NLAYERS; layer++){
        const float* Wl = inw + (long)layer*DPROJ*DM;
        inproj_kernel<<<dim3(BL/128, DZX/128), 256>>>(out, Wl);
        dtprep_kernel<<<128, 256>>>(out, Wl, dtb + layer*NH, alog + layer*NH);
        phaseA_kernel<<<BSZ*NC, 256, SMA_FLOATS*4>>>(cw + (long)layer*CONVD*DCONV,
                                                     cb + layer*CONVD);
        phaseB_kernel<<<BSZ*NH*8, 256>>>();
        phaseCG_kernel<<<BSZ*NC, 256, SMCG_FLOATS*4>>>(Dpar + layer*NH,
                                                       ow + (long)layer*DM*DI,
                                                       nw + layer*DI, out);
    }
    (void)in_sizes; (void)n_in; (void)out_size;
}

// round 5
// speedup vs baseline: 2.5213x; 1.0064x over previous
#include <cuda_runtime.h>
#include <math.h>

#define NLAYERS 4
#define DM      64
#define DS      128
#define DCONV   4
#define DI      128
#define NH      2
#define HD      64
#define CONVD   384
#define DZX     512
#define BSZ     8
#define SEQ     4096
#define BL      (BSZ*SEQ)
#define QC      64
#define NC      (SEQ/QC)
#define EPSV    1e-5f

__device__ float g_zxb [BL*(long)DZX];
__device__ float g_xbc [BL*(long)CONVD];
__device__ float g_lacc[BSZ*NH*SEQ];
__device__ float g_atot[BSZ*NH*NC];
__device__ float g_S   [(long)BSZ*NH*NC*HD*DS];
__device__ float g_hst [(long)BSZ*NH*NC*HD*DS];
__device__ float g_y   [BL*(long)DI];

__device__ __forceinline__ float siluf(float v){ return v / (1.f + __expf(-v)); }

__global__ void copy_kernel(const float* __restrict__ src, float* __restrict__ dst, int n4){
    int i = blockIdx.x*blockDim.x + threadIdx.x;
    if (i < n4) ((float4*)dst)[i] = ((const float4*)src)[i];
}

/* ---------------- in_proj GEMM ------------------------------------------- */
__global__ void inproj_kernel(const float* __restrict__ x, const float* __restrict__ W){
    __shared__ float xsT[64*132];
    __shared__ float wsT[64*132];
    int m0 = blockIdx.x * 128;
    int n0 = blockIdx.y * 128;
    int tid = threadIdx.x;
    for (int idx = tid; idx < 128*64; idx += 256){
        int m = idx >> 6, k = idx & 63;
        xsT[k*132 + m] = x[(long)(m0+m)*DM + k];
    }
    for (int idx = tid; idx < 128*64; idx += 256){
        int n = idx >> 6, k = idx & 63;
        wsT[k*132 + n] = W[(n0+n)*DM + k];
    }
    __syncthreads();
    int ty = tid >> 4, tx = tid & 15;
    float acc[8][8] = {};
    const float* pa = &xsT[ty*4];
    const float* pb = &wsT[tx*4];
    #pragma unroll 8
    for (int k = 0; k < 64; k++){
        float av[8], bw[8];
        *(float4*)&av[0] = *(const float4*)pa;
        *(float4*)&av[4] = *(const float4*)(pa + 64);
        *(float4*)&bw[0] = *(const float4*)pb;
        *(float4*)&bw[4] = *(const float4*)(pb + 64);
        pa += 132; pb += 132;
        #pragma unroll
        for (int i=0;i<8;i++)
            #pragma unroll
            for (int j=0;j<8;j++) acc[i][j] = fmaf(av[i], bw[j], acc[i][j]);
    }
    #pragma unroll
    for (int ri=0;ri<2;ri++)
        #pragma unroll
        for (int i=0;i<4;i++){
            long row = m0 + ri*64 + ty*4 + i;
            #pragma unroll
            for (int cj=0;cj<2;cj++){
                float4 v = make_float4(acc[ri*4+i][cj*4+0], acc[ri*4+i][cj*4+1],
                                       acc[ri*4+i][cj*4+2], acc[ri*4+i][cj*4+3]);
                *(float4*)&g_zxb[row*DZX + n0 + cj*64 + tx*4] = v;
            }
        }
}

/* -------- Phase A: dt scan, conv+SiLU, intra-chunk attn, chunk states ------ */
#define SMA_FLOATS (2*128*68 + 64*132 + 3*128)
__global__ void phaseA_kernel(const float* __restrict__ x, const float* __restrict__ W,
                              const float* __restrict__ dtb, const float* __restrict__ alog,
                              const float* __restrict__ cw, const float* __restrict__ cb){
    int b = blockIdx.x >> 6;
    int c = blockIdx.x & (NC-1);
    int l0 = c*QC;
    extern __shared__ float sm[];
    float* R0   = sm;                 /* B^T[s][t] -> Bsn[t][s] */
    float* R1   = sm + 128*68;        /* C^T[s][t] -> W[(h*64+tp)][t] */
    float* Xs   = sm + 2*128*68;      /* [t][p] stride 132 */
    float* la_s = Xs + 64*132;        /* [h*64+t] */
    float* dt_s = la_s + 128;
    float* cf_s = dt_s + 128;
    int tid = threadIdx.x;

    /* --- dt projection: threads 0..127 each do one (h,t) dot over k=64 --- */
    if (tid < NH*QC){
        int h = tid >> 6, t = tid & 63;
        const float* xr = x + ((long)(b*SEQ + l0 + t))*DM;
        const float* wr = W + (long)(DZX+h)*DM;
        float raw = __ldg(&dtb[h]);
        #pragma unroll
        for (int k4 = 0; k4 < 16; k4++){
            float4 w = *(const float4*)&wr[k4*4];
            float4 a = *(const float4*)&xr[k4*4];
            raw = fmaf(a.x,w.x, fmaf(a.y,w.y, fmaf(a.z,w.z, fmaf(a.w,w.w, raw))));
        }
        dt_s[tid] = (raw > 20.f) ? raw : log1pf(__expf(raw));
    }

    /* --- fused depthwise conv + SiLU from g_zxb --- */
    for (int idx = tid; idx < QC*CONVD; idx += 256){
        int t  = idx / CONVD;
        int ch = idx - t*CONVD;
        int l  = l0 + t;
        float acc = __ldg(&cb[ch]);
        #pragma unroll
        for (int k=0;k<DCONV;k++){
            int ll = l - 3 + k;
            if (ll >= 0)
                acc = fmaf(__ldg(&cw[ch*4+k]), g_zxb[((long)(b*SEQ+ll))*DZX + DI + ch], acc);
        }
        float v = siluf(acc);
        long rowb = (long)(b*SEQ + l);
        if (ch < DI){
            Xs[t*132 + ch] = v;
            g_xbc[rowb*CONVD + ch] = v;
        } else if (ch < DI+DS){
            R0[(ch-DI)*68 + t] = v;
        } else {
            R1[(ch-DI-DS)*68 + t] = v;
            g_xbc[rowb*CONVD + ch] = v;
        }
    }
    __syncthreads();

    /* --- per-head scan (warps 0,1), other warps proceed to G GEMM --- */
    int wid = tid >> 5, lane = tid & 31;
    if (wid < NH){
        int h = wid;
        float Aneg = -__expf(__ldg(&alog[h]));
        float dt0 = dt_s[h*64 + 2*lane];
        float dt1 = dt_s[h*64 + 2*lane + 1];
        float pp = (dt0 + dt1) * Aneg;
        float s = pp;
        #pragma unroll
        for (int o=1;o<32;o<<=1){ float v = __shfl_up_sync(0xffffffffu, s, o); if (lane >= o) s += v; }
        float la1 = s;
        float la0 = s - pp + dt0*Aneg;
        float at  = __shfl_sync(0xffffffffu, s, 31);
        la_s[h*64 + 2*lane]     = la0;
        la_s[h*64 + 2*lane + 1] = la1;
        cf_s[h*64 + 2*lane]     = __expf(at - la0) * dt0;
        cf_s[h*64 + 2*lane + 1] = __expf(at - la1) * dt1;
        long gbase = ((long)(b*NH + h))*SEQ + l0 + 2*lane;
        g_lacc[gbase]   = la0;
        g_lacc[gbase+1] = la1;
        if (lane == 31) g_atot[(b*NH+h)*NC + c] = at;
    }

    int ty = tid >> 4, tx = tid & 15;
    /* G[t][tp] = sum_s C[t][s]*B[tp][s] */
    float gacc[4][4] = {};
    {
        const float* pC = &R1[ty*4];
        const float* pB = &R0[tx*4];
        #pragma unroll 8
        for (int s = 0; s < DS; s++){
            float4 a  = *(const float4*)pC;
            float4 bq = *(const float4*)pB;
            pC += 68; pB += 68;
            float av[4] = {a.x,a.y,a.z,a.w};
            float bw[4] = {bq.x,bq.y,bq.z,bq.w};
            #pragma unroll
            for (int i=0;i<4;i++)
                #pragma unroll
                for (int j=0;j<4;j++) gacc[i][j] = fmaf(av[i], bw[j], gacc[i][j]);
        }
    }
    /* stage B for transpose */
    float breg[32];
    {
        int idx = tid;
        #pragma unroll
        for (int r=0;r<32;r++,idx+=256){
            int t = idx >> 7, s = idx & 127;
            breg[r] = R0[s*68 + t];
        }
    }
    __syncthreads();

    /* transpose B into R0[t][s]; build both heads' W into R1 */
    {
        int idx = tid;
        #pragma unroll
        for (int r=0;r<32;r++,idx+=256){
            int t = idx >> 7, s = idx & 127;
            R0[t*132 + s] = breg[r];
        }
    }
    #pragma unroll
    for (int h=0;h<NH;h++){
        #pragma unroll
        for (int i=0;i<4;i++){
            int t = ty*4 + i;
            float lat = la_s[h*64 + t];
            #pragma unroll
            for (int j=0;j<4;j++){
                int tp = tx*4 + j;
                float w = 0.f;
                if (tp <= t) w = __expf(lat - la_s[h*64+tp]) * dt_s[h*64+tp] * gacc[i][j];
                R1[(h*64+tp)*68 + t] = w;
            }
        }
    }
    __syncthreads();

    /* fused Y GEMM: Y[t][pg] = sum_tp W_h[t][tp]*X[tp][pg], h = pg>>6 */
    {
        int h = tx >> 3;
        float acc[4][8] = {};
        const float* pW = &R1[(h*64)*68 + ty*4];
        const float* pX = &Xs[tx*8];
        #pragma unroll 8
        for (int tp = 0; tp < QC; tp++){
            float4 a  = *(const float4*)pW;
            float4 b0 = *(const float4*)pX;
            float4 b1 = *(const float4*)(pX + 4);
            pW += 68; pX += 132;
            float av[4] = {a.x,a.y,a.z,a.w};
            float bw[8] = {b0.x,b0.y,b0.z,b0.w,b1.x,b1.y,b1.z,b1.w};
            #pragma unroll
            for (int i=0;i<4;i++)
                #pragma unroll
                for (int j=0;j<8;j++) acc[i][j] = fmaf(av[i], bw[j], acc[i][j]);
        }
        #pragma unroll
        for (int i=0;i<4;i++){
            long row = (long)(b*SEQ + l0 + ty*4 + i);
            *(float4*)&g_y[row*DI + tx*8]     = make_float4(acc[i][0],acc[i][1],acc[i][2],acc[i][3]);
            *(float4*)&g_y[row*DI + tx*8 + 4] = make_float4(acc[i][4],acc[i][5],acc[i][6],acc[i][7]);
        }
    }

    /* fused S GEMM: S[pg][s] = sum_t cf_h[t]*X[t][pg]*B[t][s], h = pg>>6 */
    {
        int h = ty >> 3;
        float acc[8][8] = {};
        const float* pX = &Xs[ty*8];
        const float* pB = &R0[tx*8];
        const float* pcf = &cf_s[h*64];
        #pragma unroll 8
        for (int t = 0; t < QC; t++){
            float cf = pcf[t];
            float4 a0 = *(const float4*)pX;
            float4 a1 = *(const float4*)(pX + 4);
            float4 b0 = *(const float4*)pB;
            float4 b1 = *(const float4*)(pB + 4);
            pX += 132; pB += 132;
            float av[8] = {a0.x*cf,a0.y*cf,a0.z*cf,a0.w*cf,a1.x*cf,a1.y*cf,a1.z*cf,a1.w*cf};
            float bw[8] = {b0.x,b0.y,b0.z,b0.w,b1.x,b1.y,b1.z,b1.w};
            #pragma unroll
            for (int i=0;i<8;i++)
                #pragma unroll
                for (int j=0;j<8;j++) acc[i][j] = fmaf(av[i], bw[j], acc[i][j]);
        }
        long base = (((long)((b*NH+h)*NC + c))*HD)*DS;
        #pragma unroll
        for (int i=0;i<8;i++){
            int p = (ty&7)*8 + i;
            *(float4*)&g_S[base + (long)p*DS + tx*8]     = make_float4(acc[i][0],acc[i][1],acc[i][2],acc[i][3]);
            *(float4*)&g_S[base + (long)p*DS + tx*8 + 4] = make_float4(acc[i][4],acc[i][5],acc[i][6],acc[i][7]);
        }
    }
}

/* ---------------- Phase B: inter-chunk recurrence, depth-2 prefetch -------- */
__global__ void phaseB_kernel(void){
    __shared__ float ea_s[NC];
    int bh   = blockIdx.x >> 3;
    int part = blockIdx.x & 7;
    int tid  = threadIdx.x;
    if (tid < NC) ea_s[tid] = __expf(g_atot[bh*NC + tid]);
    __syncthreads();
    long ebase = (long)bh*NC*(HD*DS) + part*1024 + tid*4;
    float4 h = make_float4(0.f,0.f,0.f,0.f);
    float4 buf0 = *(const float4*)&g_S[ebase];
    float4 buf1 = *(const float4*)&g_S[ebase + (long)(HD*DS)];
    #pragma unroll 2
    for (int c = 0; c < NC; c++){
        *(float4*)&g_hst[ebase + (long)c*(HD*DS)] = h;
        float ea = ea_s[c];
        float4 s = (c & 1) ? buf1 : buf0;
        h.x = fmaf(h.x, ea, s.x);
        h.y = fmaf(h.y, ea, s.y);
        h.z = fmaf(h.z, ea, s.z);
        h.w = fmaf(h.w, ea, s.w);
        if (c + 2 < NC){
            float4 nxt = *(const float4*)&g_S[ebase + (long)(c+2)*(HD*DS)];
            if (c & 1) buf1 = nxt; else buf0 = nxt;
        }
    }
}

/* ------ Phase C+G: fused inter-chunk out, gate, RMSNorm, out_proj, resid --- */
#define SMCG_FLOATS (128*68 + 128*132 + 128)
__global__ void phaseCG_kernel(const float* __restrict__ Dp, const float* __restrict__ ow,
                               const float* __restrict__ nw, float* __restrict__ xres){
    int b = blockIdx.x >> 6;
    int c = blockIdx.x & (NC-1);
    int l0 = c*QC;
    extern __shared__ float sm[];
    float* CsT2 = sm;
    float* hsT2 = sm + 128*68;
    float* yt   = hsT2;
    float* la2  = sm + 128*68 + 128*132;
    int tid = threadIdx.x;

    for (int idx = tid; idx < QC*DS; idx += 256){
        int t = idx >> 7, s = idx & 127;
        CsT2[s*68 + t] = g_xbc[((long)(b*SEQ+l0+t))*CONVD + DI + DS + s];
    }
    for (int idx = tid; idx < DS*NH*HD; idx += 256){
        int s = idx & 127, pg = idx >> 7;
        int h = pg >> 6, p = pg & 63;
        hsT2[s*132 + pg] = g_hst[(((long)((b*NH+h)*NC + c))*HD + p)*DS + s];
    }
    if (tid < NH*QC){
        int h = tid >> 6, t = tid & 63;
        la2[tid] = g_lacc[((long)(b*NH+h))*SEQ + l0 + t];
    }
    __syncthreads();

    int ty = tid >> 4, tx = tid & 15;
    int h = tx >> 3;
    float acc[4][8] = {};
    {
        const float* pC = &CsT2[ty*4];
        const float* pH = &hsT2[tx*8];
        #pragma unroll 8
        for (int s = 0; s < DS; s++){
            float4 a  = *(const float4*)pC;
            float4 b0 = *(const float4*)pH;
            float4 b1 = *(const float4*)(pH + 4);
            pC += 68; pH += 132;
            float av[4] = {a.x,a.y,a.z,a.w};
            float bw[8] = {b0.x,b0.y,b0.z,b0.w,b1.x,b1.y,b1.z,b1.w};
            #pragma unroll
            for (int i=0;i<4;i++)
                #pragma unroll
                for (int j=0;j<8;j++) acc[i][j] = fmaf(av[i], bw[j], acc[i][j]);
        }
    }
    float dh = __ldg(&Dp[h]);
    float gated[4][8];
    #pragma unroll
    for (int i=0;i<4;i++){
        int t = ty*4 + i;
        long row = (long)(b*SEQ + l0 + t);
        float e = __expf(la2[h*64 + t]);
        float4 y0 = *(const float4*)&g_y[row*DI + tx*8];
        float4 y1 = *(const float4*)&g_y[row*DI + tx*8 + 4];
        float4 x0 = *(const float4*)&g_xbc[row*CONVD + tx*8];
        float4 x1 = *(const float4*)&g_xbc[row*CONVD + tx*8 + 4];
        float4 z0 = *(const float4*)&g_zxb[row*DZX + tx*8];
        float4 z1 = *(const float4*)&g_zxb[row*DZX + tx*8 + 4];
        float yv[8] = {y0.x,y0.y,y0.z,y0.w,y1.x,y1.y,y1.z,y1.w};
        float xv[8] = {x0.x,x0.y,x0.z,x0.w,x1.x,x1.y,x1.z,x1.w};
        float zv[8] = {z0.x,z0.y,z0.z,z0.w,z1.x,z1.y,z1.z,z1.w};
        #pragma unroll
        for (int j=0;j<8;j++){
            float y = yv[j] + e*acc[i][j] + dh*xv[j];
            gated[i][j] = y * siluf(zv[j]);
        }
    }
    __syncthreads();

    #pragma unroll
    for (int i=0;i<4;i++){
        int t = ty*4 + i;
        *(float4*)&yt[t*132 + tx*8]     = make_float4(gated[i][0],gated[i][1],gated[i][2],gated[i][3]);
        *(float4*)&yt[t*132 + tx*8 + 4] = make_float4(gated[i][4],gated[i][5],gated[i][6],gated[i][7]);
    }
    for (int idx = tid; idx < DM*DI; idx += 256){
        int m = idx >> 7, k = idx & 127;
        CsT2[k*68 + m] = ow[idx];
    }
    __syncthreads();

    int wid = tid >> 5, lane = tid & 31;
    for (int r = wid*8; r < wid*8 + 8; r++){
        float s = 0.f;
        #pragma unroll
        for (int q=0;q<4;q++){ float v = yt[r*132 + lane + q*32]; s += v*v; }
        #pragma unroll
        for (int o=16;o;o>>=1) s += __shfl_xor_sync(0xffffffffu, s, o);
        float rstd = rsqrtf(s/(float)DI + EPSV);
        #pragma unroll
        for (int q=0;q<4;q++){
            int cc = lane + q*32;
            yt[r*132 + cc] *= rstd * __ldg(&nw[cc]);
        }
    }
    __syncthreads();

    float acc2[4][4] = {};
    {
        const float* p0 = &yt[(ty*4+0)*132];
        const float* p1 = &yt[(ty*4+1)*132];
        const float* p2 = &yt[(ty*4+2)*132];
        const float* p3 = &yt[(ty*4+3)*132];
        const float* pw = &CsT2[tx*4];
        #pragma unroll 8
        for (int k = 0; k < DI; k++){
            float av[4] = {p0[k], p1[k], p2[k], p3[k]};
            float4 b4 = *(const float4*)pw;
            pw += 68;
            float bw[4] = {b4.x,b4.y,b4.z,b4.w};
            #pragma unroll
            for (int i=0;i<4;i++)
                #pragma unroll
                for (int j=0;j<4;j++) acc2[i][j] = fmaf(av[i], bw[j], acc2[i][j]);
        }
    }
    #pragma unroll
    for (int i=0;i<4;i++){
        long row = (long)(b*SEQ + l0 + ty*4 + i);
        float4 old = *(float4*)&xres[row*DM + tx*4];
        old.x += acc2[i][0]; old.y += acc2[i][1];
        old.z += acc2[i][2]; old.w += acc2[i][3];
        *(float4*)&xres[row*DM + tx*4] = old;
    }
}

/* ---------------- host ----------------------------------------------------- */
extern "C" void kernel_launch(void* const* d_in, const int* in_sizes, int n_in,
                              void* d_out, int out_size){
    const float* x0    = (const float*)d_in[0];
    const float* inw   = (const float*)d_in[1];
    const float* cw    = (const float*)d_in[2];
    const float* cb    = (const float*)d_in[3];
    const float* dtb   = (const float*)d_in[4];
    const float* alog  = (const float*)d_in[5];
    const float* Dpar  = (const float*)d_in[6];
    const float* nw    = (const float*)d_in[7];
    const float* ow    = (const float*)d_in[8];
    float* out = (float*)d_out;

    cudaFuncSetAttribute(phaseA_kernel,  cudaFuncAttributeMaxDynamicSharedMemorySize, SMA_FLOATS*4);
    cudaFuncSetAttribute(phaseCG_kernel, cudaFuncAttributeMaxDynamicSharedMemorySize, SMCG_FLOATS*4);

    copy_kernel<<<(BL*DM/4+255)/256, 256>>>(x0, out, BL*DM/4);

    const int DPROJ = DZX + NH;
    for (int layer = 0; layer < NLAYERS; layer++){
        const float* Wl = inw + (long)layer*DPROJ*DM;
        inproj_kernel<<<dim3(BL/128, DZX/128), 256>>>(out, Wl);
        phaseA_kernel<<<BSZ*NC, 256, SMA_FLOATS*4>>>(out, Wl, dtb + layer*NH, alog + layer*NH,
                                                     cw + (long)layer*CONVD*DCONV,
                                                     cb + layer*CONVD);
        phaseB_kernel<<<BSZ*NH*8, 256>>>();
        phaseCG_kernel<<<BSZ*NC, 256, SMCG_FLOATS*4>>>(Dpar + layer*NH,
                                                       ow + (long)layer*DM*DI,
                                                       nw + layer*DI, out);
    }
    (void)in_sizes; (void)n_in; (void)out_size;
}

// round 6
// speedup vs baseline: 3.1251x; 1.2395x over previous
#include <cuda_runtime.h>
#include <math.h>
#include <stdint.h>

#define NLAYERS 4
#define DM      64
#define DS      128
#define DCONV   4
#define DI      128
#define NH      2
#define HD      64
#define CONVD   384
#define DZX     512
#define BSZ     8
#define SEQ     4096
#define BL      (BSZ*SEQ)
#define QC      64
#define NC      (SEQ/QC)
#define EPSV    1e-5f

__device__ float g_zxb [BL*(long)DZX];
__device__ float g_xbc [BL*(long)CONVD];
__device__ float g_lacc[BSZ*NH*SEQ];
__device__ float g_atot[BSZ*NH*NC];
__device__ float g_S   [(long)BSZ*NH*NC*HD*DS];
__device__ float g_hst [(long)BSZ*NH*NC*HD*DS];
__device__ float g_y   [BL*(long)DI];

__device__ __forceinline__ float siluf(float v){ return v / (1.f + __expf(-v)); }

/* tf32 warp mma: D(16x8) += A(16x8) * B(8x8). fp32 bits fed directly (HW truncates). */
__device__ __forceinline__ void mma8(float* d, uint32_t a0, uint32_t a1, uint32_t a2, uint32_t a3,
                                     uint32_t b0, uint32_t b1){
    asm volatile("mma.sync.aligned.m16n8k8.row.col.f32.tf32.tf32.f32 "
                 "{%0,%1,%2,%3}, {%4,%5,%6,%7}, {%8,%9}, {%0,%1,%2,%3};\n"
                 : "+f"(d[0]), "+f"(d[1]), "+f"(d[2]), "+f"(d[3])
                 : "r"(a0), "r"(a1), "r"(a2), "r"(a3), "r"(b0), "r"(b1));
}
#define F2U(v) __float_as_uint(v)

__global__ void copy_kernel(const float* __restrict__ src, float* __restrict__ dst, int n4){
    int i = blockIdx.x*blockDim.x + threadIdx.x;
    if (i < n4) ((float4*)dst)[i] = ((const float4*)src)[i];
}

/* ---------------- in_proj GEMM (tf32 mma): g_zxb = x @ W^T ----------------- */
__global__ void inproj_kernel(const float* __restrict__ x, const float* __restrict__ W){
    __shared__ float As[128*68];    /* [m][k] */
    __shared__ float Bs[64*136];    /* [k][n] */
    int m0 = blockIdx.x*128, n0 = blockIdx.y*128, tid = threadIdx.x;
    for (int idx = tid; idx < 128*16; idx += 256){
        int m = idx >> 4, k4 = idx & 15;
        *(float4*)&As[m*68 + k4*4] = *(const float4*)&x[(long)(m0+m)*DM + k4*4];
    }
    for (int idx = tid; idx < 128*64; idx += 256){
        int n = idx >> 6, k = idx & 63;
        Bs[k*136 + n] = W[(n0+n)*DM + k];
    }
    __syncthreads();
    int w = tid >> 5, lane = tid & 31, gr = lane >> 2, tg = lane & 3;
    float acc[16][4];
    #pragma unroll
    for (int j=0;j<16;j++){ acc[j][0]=acc[j][1]=acc[j][2]=acc[j][3]=0.f; }
    const float* Ar0 = &As[(w*16+gr)*68];
    const float* Ar1 = Ar0 + 8*68;
    #pragma unroll
    for (int k0 = 0; k0 < 64; k0 += 8){
        uint32_t a0 = F2U(Ar0[k0+tg]),   a1 = F2U(Ar1[k0+tg]);
        uint32_t a2 = F2U(Ar0[k0+tg+4]), a3 = F2U(Ar1[k0+tg+4]);
        const float* Bk0 = &Bs[(k0+tg)*136 + gr];
        const float* Bk1 = Bk0 + 4*136;
        #pragma unroll
        for (int j=0;j<16;j++)
            mma8(acc[j], a0,a1,a2,a3, F2U(Bk0[j*8]), F2U(Bk1[j*8]));
    }
    long row0 = m0 + w*16 + gr;
    #pragma unroll
    for (int j=0;j<16;j++){
        int col = n0 + j*8 + 2*tg;
        *(float2*)&g_zxb[row0*DZX + col]     = make_float2(acc[j][0], acc[j][1]);
        *(float2*)&g_zxb[(row0+8)*DZX + col] = make_float2(acc[j][2], acc[j][3]);
    }
}

/* -------- Phase A: dt scan, conv+SiLU, G/W/Y/S via tf32 mma ---------------- */
#define SMA_FLOATS (64*132 + 128*68 + 64*136 + 3*128)
__global__ void phaseA_kernel(const float* __restrict__ x, const float* __restrict__ W,
                              const float* __restrict__ dtb, const float* __restrict__ alog,
                              const float* __restrict__ cw, const float* __restrict__ cb){
    int b = blockIdx.x >> 6;
    int c = blockIdx.x & (NC-1);
    int l0 = c*QC;
    extern __shared__ float sm[];
    float* Cs   = sm;                   /* C [t][s] s132; later Ws [t][h*64+tp] */
    float* R0   = sm + 64*132;          /* B^T [s][t] s68 */
    float* Xs   = R0 + 128*68;          /* X [t][pg] s136 */
    float* la_s = Xs + 64*136;          /* [h*64+t] */
    float* dt_s = la_s + 128;
    float* cf_s = dt_s + 128;
    int tid = threadIdx.x;

    /* dt projection: threads 0..127, one (h,t) dot over k=64 */
    if (tid < NH*QC){
        int h = tid >> 6, t = tid & 63;
        const float* xr = x + ((long)(b*SEQ + l0 + t))*DM;
        const float* wr = W + (long)(DZX+h)*DM;
        float raw = __ldg(&dtb[h]);
        #pragma unroll
        for (int k4 = 0; k4 < 16; k4++){
            float4 wv = *(const float4*)&wr[k4*4];
            float4 a  = *(const float4*)&xr[k4*4];
            raw = fmaf(a.x,wv.x, fmaf(a.y,wv.y, fmaf(a.z,wv.z, fmaf(a.w,wv.w, raw))));
        }
        dt_s[tid] = (raw > 20.f) ? raw : log1pf(__expf(raw));
    }

    /* fused depthwise conv + SiLU from g_zxb */
    for (int idx = tid; idx < QC*CONVD; idx += 256){
        int t  = idx / CONVD;
        int ch = idx - t*CONVD;
        int l  = l0 + t;
        float acc = __ldg(&cb[ch]);
        #pragma unroll
        for (int k=0;k<DCONV;k++){
            int ll = l - 3 + k;
            if (ll >= 0)
                acc = fmaf(__ldg(&cw[ch*4+k]), g_zxb[((long)(b*SEQ+ll))*DZX + DI + ch], acc);
        }
        float v = siluf(acc);
        long rowb = (long)(b*SEQ + l);
        if (ch < DI){
            Xs[t*136 + ch] = v;
            g_xbc[rowb*CONVD + ch] = v;
        } else if (ch < DI+DS){
            R0[(ch-DI)*68 + t] = v;
        } else {
            Cs[t*132 + (ch-DI-DS)] = v;
            g_xbc[rowb*CONVD + ch] = v;
        }
    }
    __syncthreads();

    int w = tid >> 5, lane = tid & 31, gr = lane >> 2, tg = lane & 3;
    /* per-head scan (warps 0,1) */
    if (w < NH){
        int h = w;
        float Aneg = -__expf(__ldg(&alog[h]));
        float dt0 = dt_s[h*64 + 2*lane];
        float dt1 = dt_s[h*64 + 2*lane + 1];
        float pp = (dt0 + dt1) * Aneg;
        float s = pp;
        #pragma unroll
        for (int o=1;o<32;o<<=1){ float v = __shfl_up_sync(0xffffffffu, s, o); if (lane >= o) s += v; }
        float la1 = s;
        float la0 = s - pp + dt0*Aneg;
        float at  = __shfl_sync(0xffffffffu, s, 31);
        la_s[h*64 + 2*lane]     = la0;
        la_s[h*64 + 2*lane + 1] = la1;
        cf_s[h*64 + 2*lane]     = __expf(at - la0) * dt0;
        cf_s[h*64 + 2*lane + 1] = __expf(at - la1) * dt1;
        long gbase = ((long)(b*NH + h))*SEQ + l0 + 2*lane;
        g_lacc[gbase]   = la0;
        g_lacc[gbase+1] = la1;
        if (lane == 31) g_atot[(b*NH+h)*NC + c] = at;
    }

    int mt = w & 3;
    int t0 = mt*16;
    int ntb = (w >> 2)*4;
    int h = w >> 2;

    /* G GEMM: G[t][tp] = sum_s C[t][s]*B[tp][s] (4 n-tiles per warp) */
    float gfr[4][4];
    #pragma unroll
    for (int j=0;j<4;j++){ gfr[j][0]=gfr[j][1]=gfr[j][2]=gfr[j][3]=0.f; }
    {
        const float* Ar0 = &Cs[(t0+gr)*132];
        const float* Ar1 = Ar0 + 8*132;
        #pragma unroll
        for (int k0 = 0; k0 < 128; k0 += 8){
            uint32_t a0 = F2U(Ar0[k0+tg]),   a1 = F2U(Ar1[k0+tg]);
            uint32_t a2 = F2U(Ar0[k0+tg+4]), a3 = F2U(Ar1[k0+tg+4]);
            const float* Bk0 = &R0[(k0+tg)*68 + ntb*8 + gr];
            const float* Bk1 = Bk0 + 4*68;
            #pragma unroll
            for (int j=0;j<4;j++)
                mma8(gfr[j], a0,a1,a2,a3, F2U(Bk0[j*8]), F2U(Bk1[j*8]));
        }
    }
    __syncthreads();   /* G done; la/dt/cf ready */

    /* build decayed causal W (both heads) into Cs region: Ws[t][hh*64+tp] */
    #pragma unroll
    for (int hh=0; hh<NH; hh++){
        float laT0 = la_s[hh*64 + t0+gr];
        float laT1 = la_s[hh*64 + t0+gr+8];
        #pragma unroll
        for (int j=0;j<4;j++){
            int tp0 = (ntb+j)*8 + 2*tg;
            float dtp0 = dt_s[hh*64 + tp0],  dtp1 = dt_s[hh*64 + tp0+1];
            float lap0 = la_s[hh*64 + tp0],  lap1 = la_s[hh*64 + tp0+1];
            int tA = t0+gr, tB = t0+gr+8;
            float w00 = (tp0   <= tA) ? __expf(laT0-lap0)*dtp0*gfr[j][0] : 0.f;
            float w01 = (tp0+1 <= tA) ? __expf(laT0-lap1)*dtp1*gfr[j][1] : 0.f;
            float w10 = (tp0   <= tB) ? __expf(laT1-lap0)*dtp0*gfr[j][2] : 0.f;
            float w11 = (tp0+1 <= tB) ? __expf(laT1-lap1)*dtp1*gfr[j][3] : 0.f;
            Cs[tA*132 + hh*64 + tp0]   = w00;
            Cs[tA*132 + hh*64 + tp0+1] = w01;
            Cs[tB*132 + hh*64 + tp0]   = w10;
            Cs[tB*132 + hh*64 + tp0+1] = w11;
        }
    }
    __syncthreads();

    /* Y GEMM: Y[t][pg] = sum_tp Ws[t][h*64+tp]*X[tp][pg] (8 n-tiles per warp) */
    {
        float ya[8][4];
        #pragma unroll
        for (int j=0;j<8;j++){ ya[j][0]=ya[j][1]=ya[j][2]=ya[j][3]=0.f; }
        const float* Wr0 = &Cs[(t0+gr)*132 + h*64];
        const float* Wr1 = Wr0 + 8*132;
        #pragma unroll
        for (int k0 = 0; k0 < 64; k0 += 8){
            uint32_t a0 = F2U(Wr0[k0+tg]),   a1 = F2U(Wr1[k0+tg]);
            uint32_t a2 = F2U(Wr0[k0+tg+4]), a3 = F2U(Wr1[k0+tg+4]);
            const float* Bk0 = &Xs[(k0+tg)*136 + h*64 + gr];
            const float* Bk1 = Bk0 + 4*136;
            #pragma unroll
            for (int j=0;j<8;j++)
                mma8(ya[j], a0,a1,a2,a3, F2U(Bk0[j*8]), F2U(Bk1[j*8]));
        }
        long row0 = (long)(b*SEQ + l0 + t0 + gr);
        #pragma unroll
        for (int j=0;j<8;j++){
            int col = h*64 + j*8 + 2*tg;
            *(float2*)&g_y[row0*DI + col]     = make_float2(ya[j][0], ya[j][1]);
            *(float2*)&g_y[(row0+8)*DI + col] = make_float2(ya[j][2], ya[j][3]);
        }
    }

    /* S GEMM: S[pg][s] = sum_t (cf_h[t]*X[t][pg]) * B[t][s] (16 n-tiles) */
    {
        float sa[16][4];
        #pragma unroll
        for (int j=0;j<16;j++){ sa[j][0]=sa[j][1]=sa[j][2]=sa[j][3]=0.f; }
        int pg0 = w*16;
        #pragma unroll
        for (int k0 = 0; k0 < 64; k0 += 8){
            float cfA = cf_s[h*64 + k0+tg];
            float cfB = cf_s[h*64 + k0+tg+4];
            const float* Xk0 = &Xs[(k0+tg)*136 + pg0 + gr];
            const float* Xk1 = Xk0 + 4*136;
            uint32_t a0 = F2U(Xk0[0]*cfA), a1 = F2U(Xk0[8]*cfA);
            uint32_t a2 = F2U(Xk1[0]*cfB), a3 = F2U(Xk1[8]*cfB);
            #pragma unroll
            for (int j=0;j<16;j++){
                const float* Bp = &R0[(j*8+gr)*68 + k0+tg];
                mma8(sa[j], a0,a1,a2,a3, F2U(Bp[0]), F2U(Bp[4]));
            }
        }
        int p = (w&3)*16 + gr;
        long base = (((long)((b*NH+h)*NC + c))*HD)*DS;
        #pragma unroll
        for (int j=0;j<16;j++){
            int s = j*8 + 2*tg;
            *(float2*)&g_S[base + (long)p*DS + s]     = make_float2(sa[j][0], sa[j][1]);
            *(float2*)&g_S[base + (long)(p+8)*DS + s] = make_float2(sa[j][2], sa[j][3]);
        }
    }
}

/* ---------------- Phase B: inter-chunk recurrence -------------------------- */
__global__ void phaseB_kernel(void){
    __shared__ float ea_s[NC];
    int bh   = blockIdx.x >> 3;
    int part = blockIdx.x & 7;
    int tid  = threadIdx.x;
    if (tid < NC) ea_s[tid] = __expf(g_atot[bh*NC + tid]);
    __syncthreads();
    long ebase = (long)bh*NC*(HD*DS) + part*1024 + tid*4;
    float4 h = make_float4(0.f,0.f,0.f,0.f);
    float4 buf0 = *(const float4*)&g_S[ebase];
    float4 buf1 = *(const float4*)&g_S[ebase + (long)(HD*DS)];
    #pragma unroll 2
    for (int c = 0; c < NC; c++){
        *(float4*)&g_hst[ebase + (long)c*(HD*DS)] = h;
        float ea = ea_s[c];
        float4 s = (c & 1) ? buf1 : buf0;
        h.x = fmaf(h.x, ea, s.x);
        h.y = fmaf(h.y, ea, s.y);
        h.z = fmaf(h.z, ea, s.z);
        h.w = fmaf(h.w, ea, s.w);
        if (c + 2 < NC){
            float4 nxt = *(const float4*)&g_S[ebase + (long)(c+2)*(HD*DS)];
            if (c & 1) buf1 = nxt; else buf0 = nxt;
        }
    }
}

/* ------ Phase C+G (tf32 mma): inter-chunk out, gate, RMSNorm, out_proj ----- */
#define SMCG_FLOATS (64*132 + 128*136 + 128)
__global__ void phaseCG_kernel(const float* __restrict__ Dp, const float* __restrict__ ow,
                               const float* __restrict__ nw, float* __restrict__ xres){
    int b = blockIdx.x >> 6;
    int c = blockIdx.x & (NC-1);
    int l0 = c*QC;
    extern __shared__ float sm[];
    float* Cs2 = sm;                  /* C [t][s] s132; later owT [k][m] s66 */
    float* Hs  = sm + 64*132;         /* h^T [s][pg] s136; later yt [t][pg] s136 */
    float* yt  = Hs;
    float* owT = Cs2;
    float* la2 = sm + 64*132 + 128*136;
    int tid = threadIdx.x;

    for (int idx = tid; idx < QC*DS; idx += 256){
        int t = idx >> 7, s = idx & 127;
        Cs2[t*132 + s] = g_xbc[((long)(b*SEQ+l0+t))*CONVD + DI + DS + s];
    }
    for (int idx = tid; idx < DS*NH*HD; idx += 256){
        int s = idx & 127, pg = idx >> 7;
        Hs[s*136 + pg] = g_hst[(((long)((b*NH+(pg>>6))*NC + c))*HD + (pg&63))*DS + s];
    }
    if (tid < NH*QC){
        int hh = tid >> 6, t = tid & 63;
        la2[tid] = g_lacc[((long)(b*NH+hh))*SEQ + l0 + t];
    }
    __syncthreads();

    int w = tid >> 5, lane = tid & 31, gr = lane >> 2, tg = lane & 3;
    int mt = w & 3, t0 = mt*16, h = w >> 2;
    long row0 = (long)(b*SEQ + l0 + t0 + gr);
    long row1 = row0 + 8;

    /* GEMM1: Yc[t][pg] = sum_s C[t][s]*h[pg][s] (8 n-tiles per warp) */
    float acc[8][4];
    #pragma unroll
    for (int j=0;j<8;j++){ acc[j][0]=acc[j][1]=acc[j][2]=acc[j][3]=0.f; }
    {
        const float* Ar0 = &Cs2[(t0+gr)*132];
        const float* Ar1 = Ar0 + 8*132;
        #pragma unroll
        for (int k0 = 0; k0 < 128; k0 += 8){
            uint32_t a0 = F2U(Ar0[k0+tg]),   a1 = F2U(Ar1[k0+tg]);
            uint32_t a2 = F2U(Ar0[k0+tg+4]), a3 = F2U(Ar1[k0+tg+4]);
            const float* Bk0 = &Hs[(k0+tg)*136 + h*64 + gr];
            const float* Bk1 = Bk0 + 4*136;
            #pragma unroll
            for (int j=0;j<8;j++)
                mma8(acc[j], a0,a1,a2,a3, F2U(Bk0[j*8]), F2U(Bk1[j*8]));
        }
    }
    /* epilogue in registers */
    float dh = __ldg(&Dp[h]);
    float e0 = __expf(la2[h*64 + t0+gr]);
    float e1 = __expf(la2[h*64 + t0+gr+8]);
    float gated[8][4];
    #pragma unroll
    for (int j=0;j<8;j++){
        int col = h*64 + j*8 + 2*tg;
        float2 y0 = *(const float2*)&g_y  [row0*DI    + col];
        float2 x0 = *(const float2*)&g_xbc[row0*CONVD + col];
        float2 z0 = *(const float2*)&g_zxb[row0*DZX   + col];
        float2 y1 = *(const float2*)&g_y  [row1*DI    + col];
        float2 x1 = *(const float2*)&g_xbc[row1*CONVD + col];
        float2 z1 = *(const float2*)&g_zxb[row1*DZX   + col];
        gated[j][0] = (y0.x + e0*acc[j][0] + dh*x0.x) * siluf(z0.x);
        gated[j][1] = (y0.y + e0*acc[j][1] + dh*x0.y) * siluf(z0.y);
        gated[j][2] = (y1.x + e1*acc[j][2] + dh*x1.x) * siluf(z1.x);
        gated[j][3] = (y1.y + e1*acc[j][3] + dh*x1.y) * siluf(z1.y);
    }
    __syncthreads();   /* Hs reads done -> becomes yt */

    #pragma unroll
    for (int j=0;j<8;j++){
        int col = h*64 + j*8 + 2*tg;
        *(float2*)&yt[(t0+gr)*136   + col] = make_float2(gated[j][0], gated[j][1]);
        *(float2*)&yt[(t0+gr+8)*136 + col] = make_float2(gated[j][2], gated[j][3]);
    }
    for (int idx = tid; idx < DM*DI; idx += 256){
        int m = idx >> 7, k = idx & 127;
        owT[k*66 + m] = ow[idx];
    }
    __syncthreads();

    /* RMSNorm: 8 warps x 8 rows */
    for (int r = w*8; r < w*8 + 8; r++){
        float s = 0.f;
        #pragma unroll
        for (int q=0;q<4;q++){ float v = yt[r*136 + lane + q*32]; s += v*v; }
        #pragma unroll
        for (int o=16;o;o>>=1) s += __shfl_xor_sync(0xffffffffu, s, o);
        float rstd = rsqrtf(s/(float)DI + EPSV);
        #pragma unroll
        for (int q=0;q<4;q++){
            int cc = lane + q*32;
            yt[r*136 + cc] *= rstd * __ldg(&nw[cc]);
        }
    }
    __syncthreads();

    /* GEMM2: out[t][m] = sum_k yt[t][k]*ow[m][k] (4 n-tiles) + residual */
    {
        float oacc[4][4];
        #pragma unroll
        for (int j=0;j<4;j++){ oacc[j][0]=oacc[j][1]=oacc[j][2]=oacc[j][3]=0.f; }
        int ntb = (w >> 2)*4;
        const float* Ar0 = &yt[(t0+gr)*136];
        const float* Ar1 = Ar0 + 8*136;
        #pragma unroll
        for (int k0 = 0; k0 < 128; k0 += 8){
            uint32_t a0 = F2U(Ar0[k0+tg]),   a1 = F2U(Ar1[k0+tg]);
            uint32_t a2 = F2U(Ar0[k0+tg+4]), a3 = F2U(Ar1[k0+tg+4]);
            const float* Bk0 = &owT[(k0+tg)*66 + ntb*8 + gr];
            const float* Bk1 = Bk0 + 4*66;
            #pragma unroll
            for (int j=0;j<4;j++)
                mma8(oacc[j], a0,a1,a2,a3, F2U(Bk0[j*8]), F2U(Bk1[j*8]));
        }
        #pragma unroll
        for (int j=0;j<4;j++){
            int col = (ntb+j)*8 + 2*tg;
            float2 o0 = *(float2*)&xres[row0*DM + col];
            o0.x += oacc[j][0]; o0.y += oacc[j][1];
            *(float2*)&xres[row0*DM + col] = o0;
            float2 o1 = *(float2*)&xres[row1*DM + col];
            o1.x += oacc[j][2]; o1.y += oacc[j][3];
            *(float2*)&xres[row1*DM + col] = o1;
        }
    }
}

/* ---------------- host ----------------------------------------------------- */
extern "C" void kernel_launch(void* const* d_in, const int* in_sizes, int n_in,
                              void* d_out, int out_size){
    const float* x0    = (const float*)d_in[0];
    const float* inw   = (const float*)d_in[1];
    const float* cw    = (const float*)d_in[2];
    const float* cb    = (const float*)d_in[3];
    const float* dtb   = (const float*)d_in[4];
    const float* alog  = (const float*)d_in[5];
    const float* Dpar  = (const float*)d_in[6];
    const float* nw    = (const float*)d_in[7];
    const float* ow    = (const float*)d_in[8];
    float* out = (float*)d_out;

    cudaFuncSetAttribute(phaseA_kernel,  cudaFuncAttributeMaxDynamicSharedMemorySize, SMA_FLOATS*4);
    cudaFuncSetAttribute(phaseCG_kernel, cudaFuncAttributeMaxDynamicSharedMemorySize, SMCG_FLOATS*4);

    copy_kernel<<<(BL*DM/4+255)/256, 256>>>(x0, out, BL*DM/4);

    const int DPROJ = DZX + NH;
    for (int layer = 0; layer < NLAYERS; layer++){
        const float* Wl = inw + (long)layer*DPROJ*DM;
        inproj_kernel<<<dim3(BL/128, DZX/128), 256>>>(out, Wl);
        phaseA_kernel<<<BSZ*NC, 256, SMA_FLOATS*4>>>(out, Wl, dtb + layer*NH, alog + layer*NH,
                                                     cw + (long)layer*CONVD*DCONV,
                                                     cb + layer*CONVD);
        phaseB_kernel<<<BSZ*NH*8, 256>>>();
        phaseCG_kernel<<<BSZ*NC, 256, SMCG_FLOATS*4>>>(Dpar + layer*NH,
                                                       ow + (long)layer*DM*DI,
                                                       nw + layer*DI, out);
    }
    (void)in_sizes; (void)n_in; (void)out_size;
}

// round 7
// speedup vs baseline: 4.0356x; 1.2913x over previous
#include <cuda_runtime.h>
#include <math.h>
#include <stdint.h>

#define NLAYERS 4
#define DM      64
#define DS      128
#define DCONV   4
#define DI      128
#define NH      2
#define HD      64
#define CONVD   384
#define DZX     512
#define BSZ     8
#define SEQ     4096
#define BL      (BSZ*SEQ)
#define QC      64
#define NC      (SEQ/QC)
#define EPSV    1e-5f

__device__ float g_zxb [BL*(long)DZX];
__device__ float g_xbc [BL*(long)CONVD];
__device__ float g_lacc[BSZ*NH*SEQ];
__device__ float g_atot[BSZ*NH*NC];
__device__ float g_S   [(long)BSZ*NH*NC*HD*DS];
__device__ float g_hst [(long)BSZ*NH*NC*HD*DS];
__device__ float g_y   [BL*(long)DI];

__device__ __forceinline__ float siluf(float v){ return v / (1.f + __expf(-v)); }

__device__ __forceinline__ void mma8(float* d, uint32_t a0, uint32_t a1, uint32_t a2, uint32_t a3,
                                     uint32_t b0, uint32_t b1){
    asm volatile("mma.sync.aligned.m16n8k8.row.col.f32.tf32.tf32.f32 "
                 "{%0,%1,%2,%3}, {%4,%5,%6,%7}, {%8,%9}, {%0,%1,%2,%3};\n"
                 : "+f"(d[0]), "+f"(d[1]), "+f"(d[2]), "+f"(d[3])
                 : "r"(a0), "r"(a1), "r"(a2), "r"(a3), "r"(b0), "r"(b1));
}
#define F2U(v) __float_as_uint(v)

__global__ void copy_kernel(const float* __restrict__ src, float* __restrict__ dst, int n4){
    int i = blockIdx.x*blockDim.x + threadIdx.x;
    if (i < n4) ((float4*)dst)[i] = ((const float4*)src)[i];
}

/* ---------------- in_proj GEMM (tf32 mma): g_zxb = x @ W^T ----------------- */
__global__ void inproj_kernel(const float* __restrict__ x, const float* __restrict__ W){
    __shared__ float As[128*68];    /* [m][k] */
    __shared__ float Bs[64*136];    /* [k][n] */
    int m0 = blockIdx.x*128, n0 = blockIdx.y*128, tid = threadIdx.x;
    for (int idx = tid; idx < 128*16; idx += 256){
        int m = idx >> 4, k4 = idx & 15;
        *(float4*)&As[m*68 + k4*4] = *(const float4*)&x[(long)(m0+m)*DM + k4*4];
    }
    for (int idx = tid; idx < 128*64; idx += 256){
        int n = idx >> 6, k = idx & 63;
        Bs[k*136 + n] = W[(n0+n)*DM + k];
    }
    __syncthreads();
    int w = tid >> 5, lane = tid & 31, gr = lane >> 2, tg = lane & 3;
    float acc[16][4];
    #pragma unroll
    for (int j=0;j<16;j++){ acc[j][0]=acc[j][1]=acc[j][2]=acc[j][3]=0.f; }
    const float* Ar0 = &As[(w*16+gr)*68];
    const float* Ar1 = Ar0 + 8*68;
    #pragma unroll
    for (int k0 = 0; k0 < 64; k0 += 8){
        uint32_t a0 = F2U(Ar0[k0+tg]),   a1 = F2U(Ar1[k0+tg]);
        uint32_t a2 = F2U(Ar0[k0+tg+4]), a3 = F2U(Ar1[k0+tg+4]);
        const float* Bk0 = &Bs[(k0+tg)*136 + gr];
        const float* Bk1 = Bk0 + 4*136;
        #pragma unroll
        for (int j=0;j<16;j++)
            mma8(acc[j], a0,a1,a2,a3, F2U(Bk0[j*8]), F2U(Bk1[j*8]));
    }
    long row0 = m0 + w*16 + gr;
    #pragma unroll
    for (int j=0;j<16;j++){
        int col = n0 + j*8 + 2*tg;
        *(float2*)&g_zxb[row0*DZX + col]     = make_float2(acc[j][0], acc[j][1]);
        *(float2*)&g_zxb[(row0+8)*DZX + col] = make_float2(acc[j][2], acc[j][3]);
    }
}

/* -------- Phase A: dt scan, conv+SiLU (vec4), G/W/Y/S via tf32 mma --------- */
#define SMA_FLOATS (64*132 + 128*68 + 64*136 + 3*128)
__global__ void phaseA_kernel(const float* __restrict__ x, const float* __restrict__ W,
                              const float* __restrict__ dtb, const float* __restrict__ alog,
                              const float* __restrict__ cw, const float* __restrict__ cb){
    int b = blockIdx.x >> 6;
    int c = blockIdx.x & (NC-1);
    int l0 = c*QC;
    extern __shared__ float sm[];
    float* Cs   = sm;                   /* C [t][s] s132; later Ws [t][h*64+tp] */
    float* R0   = sm + 64*132;          /* B^T [s][t] s68 */
    float* Xs   = R0 + 128*68;          /* X [t][pg] s136 */
    float* la_s = Xs + 64*136;          /* [h*64+t] */
    float* dt_s = la_s + 128;
    float* cf_s = dt_s + 128;
    int tid = threadIdx.x;

    /* dt projection: threads 0..127, one (h,t) dot over k=64 */
    if (tid < NH*QC){
        int h = tid >> 6, t = tid & 63;
        const float* xr = x + ((long)(b*SEQ + l0 + t))*DM;
        const float* wr = W + (long)(DZX+h)*DM;
        float raw = __ldg(&dtb[h]);
        #pragma unroll
        for (int k4 = 0; k4 < 16; k4++){
            float4 wv = *(const float4*)&wr[k4*4];
            float4 a  = *(const float4*)&xr[k4*4];
            raw = fmaf(a.x,wv.x, fmaf(a.y,wv.y, fmaf(a.z,wv.z, fmaf(a.w,wv.w, raw))));
        }
        dt_s[tid] = (raw > 20.f) ? raw : log1pf(__expf(raw));
    }

    /* fused depthwise conv + SiLU, 4 channels per thread-iteration */
    for (int idx = tid; idx < QC*(CONVD/4); idx += 256){
        int t   = idx / (CONVD/4);
        int c4g = idx - t*(CONVD/4);
        int ch  = c4g*4;
        int l   = l0 + t;
        long rowb = (long)(b*SEQ + l);
        float4 v0 = make_float4(0.f,0.f,0.f,0.f), v1 = v0, v2 = v0, v3 = v0;
        {
            int ll;
            ll = l-3; if (ll>=0) v0 = *(const float4*)&g_zxb[((long)(b*SEQ+ll))*DZX + DI + ch];
            ll = l-2; if (ll>=0) v1 = *(const float4*)&g_zxb[((long)(b*SEQ+ll))*DZX + DI + ch];
            ll = l-1; if (ll>=0) v2 = *(const float4*)&g_zxb[((long)(b*SEQ+ll))*DZX + DI + ch];
            v3 = *(const float4*)&g_zxb[rowb*DZX + DI + ch];
        }
        float4 bias = *(const float4*)&cb[ch];
        float4 w0 = *(const float4*)&cw[ch*4];
        float4 w1 = *(const float4*)&cw[ch*4+4];
        float4 w2 = *(const float4*)&cw[ch*4+8];
        float4 w3 = *(const float4*)&cw[ch*4+12];
        float o0 = siluf(bias.x + w0.x*v0.x + w0.y*v1.x + w0.z*v2.x + w0.w*v3.x);
        float o1 = siluf(bias.y + w1.x*v0.y + w1.y*v1.y + w1.z*v2.y + w1.w*v3.y);
        float o2 = siluf(bias.z + w2.x*v0.z + w2.y*v1.z + w2.z*v2.z + w2.w*v3.z);
        float o3 = siluf(bias.w + w3.x*v0.w + w3.y*v1.w + w3.z*v2.w + w3.w*v3.w);
        float4 ov = make_float4(o0,o1,o2,o3);
        if (ch < DI){
            *(float4*)&Xs[t*136 + ch] = ov;
            *(float4*)&g_xbc[rowb*CONVD + ch] = ov;
        } else if (ch < DI+DS){
            int s = ch - DI;
            R0[(s+0)*68 + t] = o0;
            R0[(s+1)*68 + t] = o1;
            R0[(s+2)*68 + t] = o2;
            R0[(s+3)*68 + t] = o3;
        } else {
            *(float4*)&Cs[t*132 + (ch-DI-DS)] = ov;
            *(float4*)&g_xbc[rowb*CONVD + ch] = ov;
        }
    }
    __syncthreads();

    int w = tid >> 5, lane = tid & 31, gr = lane >> 2, tg = lane & 3;
    /* per-head scan (warps 0,1) */
    if (w < NH){
        int h = w;
        float Aneg = -__expf(__ldg(&alog[h]));
        float dt0 = dt_s[h*64 + 2*lane];
        float dt1 = dt_s[h*64 + 2*lane + 1];
        float pp = (dt0 + dt1) * Aneg;
        float s = pp;
        #pragma unroll
        for (int o=1;o<32;o<<=1){ float v = __shfl_up_sync(0xffffffffu, s, o); if (lane >= o) s += v; }
        float la1 = s;
        float la0 = s - pp + dt0*Aneg;
        float at  = __shfl_sync(0xffffffffu, s, 31);
        la_s[h*64 + 2*lane]     = la0;
        la_s[h*64 + 2*lane + 1] = la1;
        cf_s[h*64 + 2*lane]     = __expf(at - la0) * dt0;
        cf_s[h*64 + 2*lane + 1] = __expf(at - la1) * dt1;
        long gbase = ((long)(b*NH + h))*SEQ + l0 + 2*lane;
        g_lacc[gbase]   = la0;
        g_lacc[gbase+1] = la1;
        if (lane == 31) g_atot[(b*NH+h)*NC + c] = at;
    }

    int mt = w & 3;
    int t0 = mt*16;
    int ntb = (w >> 2)*4;
    int h = w >> 2;

    /* G GEMM: G[t][tp] = sum_s C[t][s]*B[tp][s] */
    float gfr[4][4];
    #pragma unroll
    for (int j=0;j<4;j++){ gfr[j][0]=gfr[j][1]=gfr[j][2]=gfr[j][3]=0.f; }
    {
        const float* Ar0 = &Cs[(t0+gr)*132];
        const float* Ar1 = Ar0 + 8*132;
        #pragma unroll
        for (int k0 = 0; k0 < 128; k0 += 8){
            uint32_t a0 = F2U(Ar0[k0+tg]),   a1 = F2U(Ar1[k0+tg]);
            uint32_t a2 = F2U(Ar0[k0+tg+4]), a3 = F2U(Ar1[k0+tg+4]);
            const float* Bk0 = &R0[(k0+tg)*68 + ntb*8 + gr];
            const float* Bk1 = Bk0 + 4*68;
            #pragma unroll
            for (int j=0;j<4;j++)
                mma8(gfr[j], a0,a1,a2,a3, F2U(Bk0[j*8]), F2U(Bk1[j*8]));
        }
    }
    __syncthreads();

    /* build decayed causal W (both heads): Ws[t][hh*64+tp] over Cs */
    #pragma unroll
    for (int hh=0; hh<NH; hh++){
        float laT0 = la_s[hh*64 + t0+gr];
        float laT1 = la_s[hh*64 + t0+gr+8];
        #pragma unroll
        for (int j=0;j<4;j++){
            int tp0 = (ntb+j)*8 + 2*tg;
            float dtp0 = dt_s[hh*64 + tp0],  dtp1 = dt_s[hh*64 + tp0+1];
            float lap0 = la_s[hh*64 + tp0],  lap1 = la_s[hh*64 + tp0+1];
            int tA = t0+gr, tB = t0+gr+8;
            float w00 = (tp0   <= tA) ? __expf(laT0-lap0)*dtp0*gfr[j][0] : 0.f;
            float w01 = (tp0+1 <= tA) ? __expf(laT0-lap1)*dtp1*gfr[j][1] : 0.f;
            float w10 = (tp0   <= tB) ? __expf(laT1-lap0)*dtp0*gfr[j][2] : 0.f;
            float w11 = (tp0+1 <= tB) ? __expf(laT1-lap1)*dtp1*gfr[j][3] : 0.f;
            Cs[tA*132 + hh*64 + tp0]   = w00;
            Cs[tA*132 + hh*64 + tp0+1] = w01;
            Cs[tB*132 + hh*64 + tp0]   = w10;
            Cs[tB*132 + hh*64 + tp0+1] = w11;
        }
    }
    __syncthreads();

    /* Y GEMM: Y[t][pg] = sum_tp Ws[t][h*64+tp]*X[tp][pg] */
    {
        float ya[8][4];
        #pragma unroll
        for (int j=0;j<8;j++){ ya[j][0]=ya[j][1]=ya[j][2]=ya[j][3]=0.f; }
        const float* Wr0 = &Cs[(t0+gr)*132 + h*64];
        const float* Wr1 = Wr0 + 8*132;
        #pragma unroll
        for (int k0 = 0; k0 < 64; k0 += 8){
            uint32_t a0 = F2U(Wr0[k0+tg]),   a1 = F2U(Wr1[k0+tg]);
            uint32_t a2 = F2U(Wr0[k0+tg+4]), a3 = F2U(Wr1[k0+tg+4]);
            const float* Bk0 = &Xs[(k0+tg)*136 + h*64 + gr];
            const float* Bk1 = Bk0 + 4*136;
            #pragma unroll
            for (int j=0;j<8;j++)
                mma8(ya[j], a0,a1,a2,a3, F2U(Bk0[j*8]), F2U(Bk1[j*8]));
        }
        long row0 = (long)(b*SEQ + l0 + t0 + gr);
        #pragma unroll
        for (int j=0;j<8;j++){
            int col = h*64 + j*8 + 2*tg;
            *(float2*)&g_y[row0*DI + col]     = make_float2(ya[j][0], ya[j][1]);
            *(float2*)&g_y[(row0+8)*DI + col] = make_float2(ya[j][2], ya[j][3]);
        }
    }

    /* S GEMM: S[pg][s] = sum_t (cf_h[t]*X[t][pg]) * B[t][s] */
    {
        float sa[16][4];
        #pragma unroll
        for (int j=0;j<16;j++){ sa[j][0]=sa[j][1]=sa[j][2]=sa[j][3]=0.f; }
        int pg0 = w*16;
        #pragma unroll
        for (int k0 = 0; k0 < 64; k0 += 8){
            float cfA = cf_s[h*64 + k0+tg];
            float cfB = cf_s[h*64 + k0+tg+4];
            const float* Xk0 = &Xs[(k0+tg)*136 + pg0 + gr];
            const float* Xk1 = Xk0 + 4*136;
            uint32_t a0 = F2U(Xk0[0]*cfA), a1 = F2U(Xk0[8]*cfA);
            uint32_t a2 = F2U(Xk1[0]*cfB), a3 = F2U(Xk1[8]*cfB);
            #pragma unroll
            for (int j=0;j<16;j++){
                const float* Bp = &R0[(j*8+gr)*68 + k0+tg];
                mma8(sa[j], a0,a1,a2,a3, F2U(Bp[0]), F2U(Bp[4]));
            }
        }
        int p = (w&3)*16 + gr;
        long base = (((long)((b*NH+h)*NC + c))*HD)*DS;
        #pragma unroll
        for (int j=0;j<16;j++){
            int s = j*8 + 2*tg;
            *(float2*)&g_S[base + (long)p*DS + s]     = make_float2(sa[j][0], sa[j][1]);
            *(float2*)&g_S[base + (long)(p+8)*DS + s] = make_float2(sa[j][2], sa[j][3]);
        }
    }
}

/* ---------------- Phase B: inter-chunk recurrence (256 blocks) ------------- */
__global__ void phaseB_kernel(void){
    __shared__ float ea_s[NC];
    int bh   = blockIdx.x >> 4;
    int part = blockIdx.x & 15;
    int tid  = threadIdx.x;               /* 128 threads */
    if (tid < NC) ea_s[tid] = __expf(g_atot[bh*NC + tid]);
    __syncthreads();
    long ebase = (long)bh*NC*(HD*DS) + part*512 + tid*4;
    float4 h = make_float4(0.f,0.f,0.f,0.f);
    float4 buf0 = *(const float4*)&g_S[ebase];
    float4 buf1 = *(const float4*)&g_S[ebase + (long)(HD*DS)];
    #pragma unroll 2
    for (int c = 0; c < NC; c++){
        *(float4*)&g_hst[ebase + (long)c*(HD*DS)] = h;
        float ea = ea_s[c];
        float4 s = (c & 1) ? buf1 : buf0;
        h.x = fmaf(h.x, ea, s.x);
        h.y = fmaf(h.y, ea, s.y);
        h.z = fmaf(h.z, ea, s.z);
        h.w = fmaf(h.w, ea, s.w);
        if (c + 2 < NC){
            float4 nxt = *(const float4*)&g_S[ebase + (long)(c+2)*(HD*DS)];
            if (c & 1) buf1 = nxt; else buf0 = nxt;
        }
    }
}

/* ------ Phase C+G (tf32 mma): inter-chunk out, gate, RMSNorm, out_proj ----- */
#define SMCG_FLOATS (64*132 + 128*136 + 128)
__global__ void phaseCG_kernel(const float* __restrict__ Dp, const float* __restrict__ ow,
                               const float* __restrict__ nw, float* __restrict__ xres){
    int b = blockIdx.x >> 6;
    int c = blockIdx.x & (NC-1);
    int l0 = c*QC;
    extern __shared__ float sm[];
    float* Cs2 = sm;                  /* C [t][s] s132; later owT [k][m] s66 */
    float* Hs  = sm + 64*132;         /* h^T [s][pg] s136; later yt [t][pg] s136 */
    float* yt  = Hs;
    float* owT = Cs2;
    float* la2 = sm + 64*132 + 128*136;
    int tid = threadIdx.x;

    for (int idx = tid; idx < QC*(DS/4); idx += 256){
        int t = idx >> 5, s4 = (idx & 31)*4;
        *(float4*)&Cs2[t*132 + s4] =
            *(const float4*)&g_xbc[((long)(b*SEQ+l0+t))*CONVD + DI + DS + s4];
    }
    for (int idx = tid; idx < DS*NH*HD; idx += 256){
        int s = idx & 127, pg = idx >> 7;
        Hs[s*136 + pg] = g_hst[(((long)((b*NH+(pg>>6))*NC + c))*HD + (pg&63))*DS + s];
    }
    if (tid < NH*QC){
        int hh = tid >> 6, t = tid & 63;
        la2[tid] = g_lacc[((long)(b*NH+hh))*SEQ + l0 + t];
    }
    __syncthreads();

    int w = tid >> 5, lane = tid & 31, gr = lane >> 2, tg = lane & 3;
    int mt = w & 3, t0 = mt*16, h = w >> 2;
    long row0 = (long)(b*SEQ + l0 + t0 + gr);
    long row1 = row0 + 8;

    /* GEMM1: Yc[t][pg] = sum_s C[t][s]*h[pg][s] */
    float acc[8][4];
    #pragma unroll
    for (int j=0;j<8;j++){ acc[j][0]=acc[j][1]=acc[j][2]=acc[j][3]=0.f; }
    {
        const float* Ar0 = &Cs2[(t0+gr)*132];
        const float* Ar1 = Ar0 + 8*132;
        #pragma unroll
        for (int k0 = 0; k0 < 128; k0 += 8){
            uint32_t a0 = F2U(Ar0[k0+tg]),   a1 = F2U(Ar1[k0+tg]);
            uint32_t a2 = F2U(Ar0[k0+tg+4]), a3 = F2U(Ar1[k0+tg+4]);
            const float* Bk0 = &Hs[(k0+tg)*136 + h*64 + gr];
            const float* Bk1 = Bk0 + 4*136;
            #pragma unroll
            for (int j=0;j<8;j++)
                mma8(acc[j], a0,a1,a2,a3, F2U(Bk0[j*8]), F2U(Bk1[j*8]));
        }
    }
    float dh = __ldg(&Dp[h]);
    float e0 = __expf(la2[h*64 + t0+gr]);
    float e1 = __expf(la2[h*64 + t0+gr+8]);
    float gated[8][4];
    #pragma unroll
    for (int j=0;j<8;j++){
        int col = h*64 + j*8 + 2*tg;
        float2 y0 = *(const float2*)&g_y  [row0*DI    + col];
        float2 x0 = *(const float2*)&g_xbc[row0*CONVD + col];
        float2 z0 = *(const float2*)&g_zxb[row0*DZX   + col];
        float2 y1 = *(const float2*)&g_y  [row1*DI    + col];
        float2 x1 = *(const float2*)&g_xbc[row1*CONVD + col];
        float2 z1 = *(const float2*)&g_zxb[row1*DZX   + col];
        gated[j][0] = (y0.x + e0*acc[j][0] + dh*x0.x) * siluf(z0.x);
        gated[j][1] = (y0.y + e0*acc[j][1] + dh*x0.y) * siluf(z0.y);
        gated[j][2] = (y1.x + e1*acc[j][2] + dh*x1.x) * siluf(z1.x);
        gated[j][3] = (y1.y + e1*acc[j][3] + dh*x1.y) * siluf(z1.y);
    }
    __syncthreads();

    #pragma unroll
    for (int j=0;j<8;j++){
        int col = h*64 + j*8 + 2*tg;
        *(float2*)&yt[(t0+gr)*136   + col] = make_float2(gated[j][0], gated[j][1]);
        *(float2*)&yt[(t0+gr+8)*136 + col] = make_float2(gated[j][2], gated[j][3]);
    }
    for (int idx = tid; idx < DM*DI; idx += 256){
        int m = idx >> 7, k = idx & 127;
        owT[k*66 + m] = ow[idx];
    }
    __syncthreads();

    /* RMSNorm: 8 warps x 8 rows */
    for (int r = w*8; r < w*8 + 8; r++){
        float s = 0.f;
        #pragma unroll
        for (int q=0;q<4;q++){ float v = yt[r*136 + lane + q*32]; s += v*v; }
        #pragma unroll
        for (int o=16;o;o>>=1) s += __shfl_xor_sync(0xffffffffu, s, o);
        float rstd = rsqrtf(s/(float)DI + EPSV);
        #pragma unroll
        for (int q=0;q<4;q++){
            int cc = lane + q*32;
            yt[r*136 + cc] *= rstd * __ldg(&nw[cc]);
        }
    }
    __syncthreads();

    /* GEMM2: out[t][m] = sum_k yt[t][k]*ow[m][k] + residual */
    {
        float oacc[4][4];
        #pragma unroll
        for (int j=0;j<4;j++){ oacc[j][0]=oacc[j][1]=oacc[j][2]=oacc[j][3]=0.f; }
        int ntb = (w >> 2)*4;
        const float* Ar0 = &yt[(t0+gr)*136];
        const float* Ar1 = Ar0 + 8*136;
        #pragma unroll
        for (int k0 = 0; k0 < 128; k0 += 8){
            uint32_t a0 = F2U(Ar0[k0+tg]),   a1 = F2U(Ar1[k0+tg]);
            uint32_t a2 = F2U(Ar0[k0+tg+4]), a3 = F2U(Ar1[k0+tg+4]);
            const float* Bk0 = &owT[(k0+tg)*66 + ntb*8 + gr];
            const float* Bk1 = Bk0 + 4*66;
            #pragma unroll
            for (int j=0;j<4;j++)
                mma8(oacc[j], a0,a1,a2,a3, F2U(Bk0[j*8]), F2U(Bk1[j*8]));
        }
        #pragma unroll
        for (int j=0;j<4;j++){
            int col = (ntb+j)*8 + 2*tg;
            float2 o0 = *(float2*)&xres[row0*DM + col];
            o0.x += oacc[j][0]; o0.y += oacc[j][1];
            *(float2*)&xres[row0*DM + col] = o0;
            float2 o1 = *(float2*)&xres[row1*DM + col];
            o1.x += oacc[j][2]; o1.y += oacc[j][3];
            *(float2*)&xres[row1*DM + col] = o1;
        }
    }
}

/* ---------------- host ----------------------------------------------------- */
extern "C" void kernel_launch(void* const* d_in, const int* in_sizes, int n_in,
                              void* d_out, int out_size){
    const float* x0    = (const float*)d_in[0];
    const float* inw   = (const float*)d_in[1];
    const float* cw    = (const float*)d_in[2];
    const float* cb    = (const float*)d_in[3];
    const float* dtb   = (const float*)d_in[4];
    const float* alog  = (const float*)d_in[5];
    const float* Dpar  = (const float*)d_in[6];
    const float* nw    = (const float*)d_in[7];
    const float* ow    = (const float*)d_in[8];
    float* out = (float*)d_out;

    cudaFuncSetAttribute(phaseA_kernel,  cudaFuncAttributeMaxDynamicSharedMemorySize, SMA_FLOATS*4);
    cudaFuncSetAttribute(phaseCG_kernel, cudaFuncAttributeMaxDynamicSharedMemorySize, SMCG_FLOATS*4);

    copy_kernel<<<(BL*DM/4+255)/256, 256>>>(x0, out, BL*DM/4);

    const int DPROJ = DZX + NH;
    for (int layer = 0; layer < NLAYERS; layer++){
        const float* Wl = inw + (long)layer*DPROJ*DM;
        inproj_kernel<<<dim3(BL/128, DZX/128), 256>>>(out, Wl);
        phaseA_kernel<<<BSZ*NC, 256, SMA_FLOATS*4>>>(out, Wl, dtb + layer*NH, alog + layer*NH,
                                                     cw + (long)layer*CONVD*DCONV,
                                                     cb + layer*CONVD);
        phaseB_kernel<<<BSZ*NH*16, 128>>>();
        phaseCG_kernel<<<BSZ*NC, 256, SMCG_FLOATS*4>>>(Dpar + layer*NH,
                                                       ow + (long)layer*DM*DI,
                                                       nw + layer*DI, out);
    }
    (void)in_sizes; (void)n_in; (void)out_size;
}